// round 11
// baseline (speedup 1.0000x reference)
#include <cuda_runtime.h>
#include <math.h>

#define BB 8
#define SS 16
#define HH 16
#define DD 128
#define EE 2048
#define MM 128          // B*S rows
#define TCACHE 4096

// ---------------- scratch (device globals) ----------------------------------
__device__ float g_q[MM * EE];           // (b,h,s,d): ((b*16+h)*16+s)*128+d
__device__ float g_ctx[MM * EE];         // (b,s,e) row-major
__device__ float g_part[2 * 128 * 16 * 128];  // [split][bh][q][d] unnormalized
__device__ float g_ml[2 * 128 * 16 * 2];      // [split][bh][q][{m,l}]

// ---------------- f32x2 helpers ---------------------------------------------
__device__ __forceinline__ void ffma2(unsigned long long& d,
                                      unsigned long long a,
                                      unsigned long long b) {
    asm("fma.rn.f32x2 %0, %1, %2, %0;" : "+l"(d) : "l"(a), "l"(b));
}
__device__ __forceinline__ void fmul2(unsigned long long& d,
                                      unsigned long long b) {
    asm("mul.rn.f32x2 %0, %0, %1;" : "+l"(d) : "l"(b));
}
__device__ __forceinline__ unsigned long long dup2(float x) {
    unsigned long long r;
    unsigned xi = __float_as_uint(x);
    asm("mov.b64 %0, {%1, %2};" : "=l"(r) : "r"(xi), "r"(xi));
    return r;
}
__device__ __forceinline__ float lo32(unsigned long long v) {
    return __uint_as_float((unsigned)(v & 0xffffffffull));
}
__device__ __forceinline__ float hi32(unsigned long long v) {
    return __uint_as_float((unsigned)(v >> 32));
}

// =============================================================================
// GEMM body: Y(tile 64m x 64n) = X @ W^T + b.  BK=32, 128 threads.
// Thread tile: 4m (scalar, dup'd) x 8n (4 f32x2 pairs).
// Per k: 4 LDS.32 + 4 LDS.64 + 16 ffma2.  BK=32 => ~1000-cyc compute window
// fully covers the register-prefetched global loads of the next k-tile.
// MODE 0: out[m*2048 + f]
// MODE 1: out[((b*16+h)*16+s)*128+d], b=m>>4, s=m&15, h=f>>7, d=f&127
// =============================================================================
template <int MODE>
__device__ __forceinline__ void gemm_body(const float* __restrict__ X,
                                          const float* __restrict__ W,
                                          const float* __restrict__ bias,
                                          float* __restrict__ out) {
    __shared__ __align__(16) float Xs[32 * 68];  // [k][m], stride 68 (even!)
    __shared__ __align__(16) float Ws[32 * 68];  // [k][n]

    int tid = threadIdx.x;
    int m0 = blockIdx.y * 64;
    int f0 = blockIdx.x * 64;
    int lr = tid >> 1;            // load row 0..63
    int lc = (tid & 1) * 16;      // k-col base 0 or 16
    int mg = tid & 15;            // m = m0 + mg + 16*mm
    int ng = tid >> 4;            // f = f0 + ng*8 + 2*np + {0,1}

    float4 xp[4], wp[4];
#pragma unroll
    for (int i = 0; i < 4; i++) {
        xp[i] = *reinterpret_cast<const float4*>(X + (size_t)(m0 + lr) * EE + lc + 4 * i);
        wp[i] = *reinterpret_cast<const float4*>(W + (size_t)(f0 + lr) * EE + lc + 4 * i);
    }

    unsigned long long acc[4][4] = {};  // [mm][np]

    for (int kt = 0; kt < EE; kt += 32) {
        __syncthreads();
#pragma unroll
        for (int i = 0; i < 4; i++) {
            Xs[(lc + 4 * i + 0) * 68 + lr] = xp[i].x;
            Xs[(lc + 4 * i + 1) * 68 + lr] = xp[i].y;
            Xs[(lc + 4 * i + 2) * 68 + lr] = xp[i].z;
            Xs[(lc + 4 * i + 3) * 68 + lr] = xp[i].w;
            Ws[(lc + 4 * i + 0) * 68 + lr] = wp[i].x;
            Ws[(lc + 4 * i + 1) * 68 + lr] = wp[i].y;
            Ws[(lc + 4 * i + 2) * 68 + lr] = wp[i].z;
            Ws[(lc + 4 * i + 3) * 68 + lr] = wp[i].w;
        }
        __syncthreads();
        if (kt + 32 < EE) {
#pragma unroll
            for (int i = 0; i < 4; i++) {
                xp[i] = *reinterpret_cast<const float4*>(
                    X + (size_t)(m0 + lr) * EE + kt + 32 + lc + 4 * i);
                wp[i] = *reinterpret_cast<const float4*>(
                    W + (size_t)(f0 + lr) * EE + kt + 32 + lc + 4 * i);
            }
        }
#pragma unroll
        for (int k = 0; k < 32; k++) {
            unsigned long long a2[4];
#pragma unroll
            for (int mm = 0; mm < 4; mm++)
                a2[mm] = dup2(Xs[k * 68 + mg + 16 * mm]);
            unsigned long long bp[4];
#pragma unroll
            for (int np = 0; np < 4; np++)
                bp[np] = *reinterpret_cast<const unsigned long long*>(
                    &Ws[k * 68 + ng * 8 + 2 * np]);
#pragma unroll
            for (int mm = 0; mm < 4; mm++)
#pragma unroll
                for (int np = 0; np < 4; np++)
                    ffma2(acc[mm][np], a2[mm], bp[np]);
        }
    }

#pragma unroll
    for (int np = 0; np < 4; np++) {
        int f = f0 + ng * 8 + 2 * np;   // even
        float b0 = bias[f], b1 = bias[f + 1];
#pragma unroll
        for (int mm = 0; mm < 4; mm++) {
            int m = m0 + mg + 16 * mm;
            float2 v;
            v.x = lo32(acc[mm][np]) + b0;
            v.y = hi32(acc[mm][np]) + b1;
            if (MODE == 0) {
                *reinterpret_cast<float2*>(out + (size_t)m * EE + f) = v;
            } else {
                int b = m >> 4, s = m & 15, h = f >> 7, d = f & 127;
                *reinterpret_cast<float2*>(
                    out + (((size_t)(b * HH + h)) * SS + s) * DD + d) = v;
            }
        }
    }
}

__global__ void __launch_bounds__(128, 4) qkv_gemm(const float* __restrict__ emb,
                                                   const float* __restrict__ Wq,
                                                   const float* __restrict__ Wk,
                                                   const float* __restrict__ Wv,
                                                   const float* __restrict__ bq,
                                                   const float* __restrict__ bk,
                                                   const float* __restrict__ bv,
                                                   float* __restrict__ kout,
                                                   float* __restrict__ vout) {
    const float* W;
    const float* bias;
    float* o;
    if (blockIdx.z == 0) { W = Wq; bias = bq; o = g_q; }
    else if (blockIdx.z == 1) { W = Wk; bias = bk; o = kout; }
    else { W = Wv; bias = bv; o = vout; }
    gemm_body<1>(emb, W, bias, o);
}

__global__ void __launch_bounds__(128, 4) out_gemm(const float* __restrict__ Wo,
                                                   const float* __restrict__ bo,
                                                   float* __restrict__ out) {
    gemm_body<0>(g_ctx, Wo, bo, out);
}

// =============================================================================
// Flash attention, split-KV x2: CTA (split, bh) handles 64 (or 65) 32-key
// tiles. 256 threads, 2 CTAs/SM. Q in registers; score partials staged
// through the plane aliasing Vs; fused warp-per-row reduce+softmax.
// Outputs UNNORMALIZED o-hat plus (m, l) per row; combine kernel merges.
// =============================================================================
__global__ void __launch_bounds__(256, 2) flash_kernel(const float* __restrict__ kc,
                                                       const float* __restrict__ vc,
                                                       const float* __restrict__ knew,
                                                       const float* __restrict__ vnew) {
    // SM[0:4224)    = Ks[j][132]
    // SM[4224:8448) = Vs[j][132]  (aliases SP[dg][16][33] during scores/reduce)
    // SM[0:8448)    = FB[256][33] for the final o reduction
    __shared__ __align__(16) float SM[8448];
    __shared__ float Ss[16 * 34];
    __shared__ float m_s[16], l_s[16], c_s[16];

    float* Ks = SM;
    float* Vs = SM + 4224;
    float* SP = SM + 4224;
    float* FB = SM;

    int tid = threadIdx.x;
    int bh = blockIdx.x & 127;
    int split = blockIdx.x >> 7;

    // --- scores ids ----------------------------------------------------------
    int qgA = tid & 3;          // 4 groups x 4 queries
    int kgA = (tid >> 2) & 7;   // keys j = kgA + 8*kk
    int dgA = tid >> 5;         // d in [dgA*16, dgA*16+16)

    unsigned long long qreg[4][8];
    {
        const float* qb = g_q + (size_t)bh * (SS * DD);
#pragma unroll
        for (int qq = 0; qq < 4; qq++)
#pragma unroll
            for (int dp = 0; dp < 8; dp++)
                qreg[qq][dp] = *reinterpret_cast<const unsigned long long*>(
                    qb + (qgA * 4 + qq) * DD + dgA * 16 + 2 * dp);
    }

    // --- PV ids --------------------------------------------------------------
    int dg2 = tid & 15;          // d = 2*dg2 + 32*r
    int qg2 = (tid >> 4) & 3;    // 4 groups x 4 queries
    int ksl = tid >> 6;          // 4 key slices x 8 keys
    unsigned long long o2[4][4] = {};  // [qq][r]

    // --- softmax ids ---------------------------------------------------------
    int warp = tid >> 5;
    int lane = tid & 31;

    if (tid < 16) { m_s[tid] = -1e30f; l_s[tid] = 0.f; }

    // --- K/V loader ids ------------------------------------------------------
    int jl = tid >> 3;           // row 0..31
    int cl = tid & 7;            // float4 cols cl, cl+8, cl+16, cl+24

    const float scale = 0.08838834764831845f;  // 1/sqrt(128)

    const int t0 = split * 64;
    const int NT = split ? 65 : 64;   // split 1 owns the 16-key tail tile

    float4 kpre[4], vpre[4];
    {
        const float* ks0 = kc + ((size_t)bh * TCACHE + (size_t)t0 * 32) * DD;
#pragma unroll
        for (int t = 0; t < 4; t++)
            kpre[t] = *reinterpret_cast<const float4*>(ks0 + (size_t)jl * DD + cl * 4 + 32 * t);
    }

    for (int lt = 0; lt < NT; lt++) {
        int tile = t0 + lt;
        bool tail = (tile == 128);
        bool on = !tail || (jl < 16);

        // STS K (prefetched)
        if (on) {
#pragma unroll
            for (int t = 0; t < 4; t++)
                *reinterpret_cast<float4*>(&Ks[jl * 132 + cl * 4 + 32 * t]) = kpre[t];
        }
        __syncthreads();  // (a) K visible

        // scores: acc[qq][kk] over this thread's 16 d's
        {
            unsigned long long acc[4][4] = {};
#pragma unroll
            for (int dp = 0; dp < 8; dp++) {
#pragma unroll
                for (int kk = 0; kk < 4; kk++) {
                    unsigned long long kv =
                        *reinterpret_cast<const unsigned long long*>(
                            &Ks[(kgA + 8 * kk) * 132 + dgA * 16 + 2 * dp]);
#pragma unroll
                    for (int qq = 0; qq < 4; qq++)
                        ffma2(acc[qq][kk], qreg[qq][dp], kv);
                }
            }
#pragma unroll
            for (int qq = 0; qq < 4; qq++)
#pragma unroll
                for (int kk = 0; kk < 4; kk++)
                    SP[dgA * 528 + (qgA * 4 + qq) * 33 + (kgA + 8 * kk)] =
                        lo32(acc[qq][kk]) + hi32(acc[qq][kk]);
        }
        __syncthreads();  // (b) SP complete

        // V LDG into registers (latency covered by reduce+softmax + co-CTA)
        {
            const float* vsrc = !tail
                ? vc + ((size_t)bh * TCACHE + (size_t)tile * 32) * DD
                : vnew + (size_t)bh * (SS * DD);
            if (on) {
#pragma unroll
                for (int t = 0; t < 4; t++)
                    vpre[t] = *reinterpret_cast<const float4*>(
                        vsrc + (size_t)jl * DD + cl * 4 + 32 * t);
            }
        }

        // fused reduce + online softmax: warp w owns rows w and w+8, lane=k
#pragma unroll
        for (int rr = 0; rr < 2; rr++) {
            int row = warp + 8 * rr;
            float s = 0.f;
#pragma unroll
            for (int dg = 0; dg < 8; dg++) s += SP[dg * 528 + row * 33 + lane];
            s *= scale;
            if (tail && lane > row) s = -1e30f;  // also kills stale k>=16 slots
            float mx = s;
#pragma unroll
            for (int off = 16; off; off >>= 1)
                mx = fmaxf(mx, __shfl_xor_sync(0xffffffffu, mx, off));
            float mold = m_s[row];
            float mnew = fmaxf(mold, mx);
            float p = __expf(s - mnew);
            Ss[row * 34 + lane] = p;
            float sum = p;
#pragma unroll
            for (int off = 16; off; off >>= 1)
                sum += __shfl_xor_sync(0xffffffffu, sum, off);
            if (lane == 0) {
                float c = __expf(mold - mnew);
                m_s[row] = mnew;
                l_s[row] = l_s[row] * c + sum;
                c_s[row] = c;
            }
        }
        __syncthreads();  // (c) SP consumed, Ss/c_s ready

        // STS V (over SP region)
        if (on) {
#pragma unroll
            for (int t = 0; t < 4; t++)
                *reinterpret_cast<float4*>(&Vs[jl * 132 + cl * 4 + 32 * t]) = vpre[t];
        }
        __syncthreads();  // (d) V ready

        // prefetch NEXT tile K (lands during PV)
        if (lt + 1 < NT) {
            int tn = tile + 1;
            bool ntail = (tn == 128);
            const float* ksrc = !ntail
                ? kc + ((size_t)bh * TCACHE + (size_t)tn * 32) * DD
                : knew + (size_t)bh * (SS * DD);
            if (!ntail || jl < 16) {
#pragma unroll
                for (int t = 0; t < 4; t++)
                    kpre[t] = *reinterpret_cast<const float4*>(
                        ksrc + (size_t)jl * DD + cl * 4 + 32 * t);
            }
        }

        // PV: o = o*c + P @ V on this thread's key slice
        {
            unsigned long long cf[4];
#pragma unroll
            for (int qq = 0; qq < 4; qq++) cf[qq] = dup2(c_s[qg2 * 4 + qq]);
#pragma unroll
            for (int qq = 0; qq < 4; qq++)
#pragma unroll
                for (int r = 0; r < 4; r++) fmul2(o2[qq][r], cf[qq]);

#pragma unroll
            for (int jj = 0; jj < 8; jj++) {
                int j = ksl * 8 + jj;
                unsigned long long pf[4];
#pragma unroll
                for (int qq = 0; qq < 4; qq++)
                    pf[qq] = dup2(Ss[(qg2 * 4 + qq) * 34 + j]);
#pragma unroll
                for (int r = 0; r < 4; r++) {
                    unsigned long long vv =
                        *reinterpret_cast<const unsigned long long*>(
                            &Vs[j * 132 + 2 * dg2 + 32 * r]);
#pragma unroll
                    for (int qq = 0; qq < 4; qq++) ffma2(o2[qq][r], pf[qq], vv);
                }
            }
        }
    }

    // epilogue: store (m, l); reduce 4 key-slice partials; write UNNORMALIZED
    __syncthreads();
    if (tid < 16) {
        g_ml[((size_t)(split * 128 + bh) * 16 + tid) * 2 + 0] = m_s[tid];
        g_ml[((size_t)(split * 128 + bh) * 16 + tid) * 2 + 1] = l_s[tid];
    }
#pragma unroll
    for (int qq = 0; qq < 4; qq++)
#pragma unroll
        for (int r = 0; r < 4; r++) {
            FB[tid * 33 + qq * 8 + r * 2]     = lo32(o2[qq][r]);
            FB[tid * 33 + qq * 8 + r * 2 + 1] = hi32(o2[qq][r]);
        }
    __syncthreads();
    if (tid < 64) {
        float* dst = g_part + ((size_t)(split * 128 + bh)) * (SS * DD);
#pragma unroll
        for (int i = 0; i < 32; i++) {
            float v = FB[tid * 33 + i] + FB[(tid + 64) * 33 + i] +
                      FB[(tid + 128) * 33 + i] + FB[(tid + 192) * 33 + i];
            int qq = i >> 3, r = (i >> 1) & 3, lh = i & 1;
            int q = qg2 * 4 + qq;
            int d = 2 * dg2 + 32 * r + lh;
            dst[q * DD + d] = v;
        }
    }
}

// =============================================================================
// Combine the two KV-splits: o = (o0*e^(m0-M) + o1*e^(m1-M)) / (l0*e0 + l1*e1)
// =============================================================================
__global__ void __launch_bounds__(256) combine_kernel() {
    __shared__ float w0s[16], w1s[16];
    int bh = blockIdx.x;
    int tid = threadIdx.x;
    if (tid < 16) {
        float m0 = g_ml[((size_t)bh * 16 + tid) * 2 + 0];
        float l0 = g_ml[((size_t)bh * 16 + tid) * 2 + 1];
        float m1 = g_ml[((size_t)(128 + bh) * 16 + tid) * 2 + 0];
        float l1 = g_ml[((size_t)(128 + bh) * 16 + tid) * 2 + 1];
        float M = fmaxf(m0, m1);
        float e0 = __expf(m0 - M), e1 = __expf(m1 - M);
        float inv = 1.f / (l0 * e0 + l1 * e1);
        w0s[tid] = e0 * inv;
        w1s[tid] = e1 * inv;
    }
    __syncthreads();
    int b = bh >> 4, h = bh & 15;
    const float* p0 = g_part + (size_t)bh * (SS * DD);
    const float* p1 = g_part + (size_t)(128 + bh) * (SS * DD);
    for (int idx = tid; idx < SS * DD; idx += 256) {
        int q = idx >> 7;
        g_ctx[((size_t)(b * SS + q)) * EE + h * DD + (idx & 127)] =
            p0[idx] * w0s[q] + p1[idx] * w1s[q];
    }
}

// ---------------- launch -----------------------------------------------------
extern "C" void kernel_launch(void* const* d_in, const int* in_sizes, int n_in,
                              void* d_out, int out_size) {
    const float* emb = (const float*)d_in[0];
    const float* kc  = (const float*)d_in[1];
    const float* vc  = (const float*)d_in[2];
    const float* Wq  = (const float*)d_in[3];
    const float* bq  = (const float*)d_in[4];
    const float* Wk  = (const float*)d_in[5];
    const float* bk  = (const float*)d_in[6];
    const float* Wv  = (const float*)d_in[7];
    const float* bv  = (const float*)d_in[8];
    const float* Wo  = (const float*)d_in[9];
    const float* bo  = (const float*)d_in[10];

    float* out  = (float*)d_out;          // (8,16,2048)
    float* kout = out + MM * EE;          // k_new (8,16,16,128)
    float* vout = out + 2 * MM * EE;      // v_new (8,16,16,128)

    qkv_gemm<<<dim3(32, 2, 3), 128>>>(emb, Wq, Wk, Wv, bq, bk, bv, kout, vout);
    flash_kernel<<<256, 256>>>(kc, vc, kout, vout);
    combine_kernel<<<128, 256>>>();
    out_gemm<<<dim3(32, 2, 1), 128>>>(Wo, bo, out);
}

// round 13
// speedup vs baseline: 1.0921x; 1.0921x over previous
#include <cuda_runtime.h>
#include <math.h>

#define BB 8
#define SS 16
#define HH 16
#define DD 128
#define EE 2048
#define MM 128          // B*S rows
#define TCACHE 4096

typedef unsigned long long ull;

// ---------------- scratch (device globals) ----------------------------------
__device__ float g_q[MM * EE];                // (b,h,s,d)
__device__ float g_ctx[MM * EE];              // (b,s,e)
__device__ float g_part[2 * 128 * 16 * 128];  // [split][bh][q][d] unnormalized
__device__ float g_ml[2 * 128 * 16 * 2];      // [split][bh][q][{m,l}]

// ---------------- f32x2 helpers ---------------------------------------------
__device__ __forceinline__ void ffma2(ull& d, ull a, ull b) {
    asm("fma.rn.f32x2 %0, %1, %2, %0;" : "+l"(d) : "l"(a), "l"(b));
}
__device__ __forceinline__ void fmul2(ull& d, ull b) {
    asm("mul.rn.f32x2 %0, %0, %1;" : "+l"(d) : "l"(b));
}
__device__ __forceinline__ ull pack2(float a, float b) {
    ull r;
    asm("mov.b64 %0, {%1, %2};" : "=l"(r) : "f"(a), "f"(b));
    return r;
}
__device__ __forceinline__ ull dup2(float x) { return pack2(x, x); }
__device__ __forceinline__ float lo32(ull v) {
    return __uint_as_float((unsigned)(v & 0xffffffffull));
}
__device__ __forceinline__ float hi32(ull v) {
    return __uint_as_float((unsigned)(v >> 32));
}

// =============================================================================
// GEMM body: 32x32 tile, BK=32, 64 threads. Thread tile 4m(2 f32x2 pairs)x4n.
// BK=32 compute window (~500 cyc) covers L2 latency; small tiles give
// grid 768 (qkv) / 256 (out) for 5+/1.7+ CTAs per SM.
// MODE 0: out[m*2048+f];  MODE 1: out[((b*16+h)*16+s)*128+d]
// =============================================================================
template <int MODE>
__device__ __forceinline__ void gemm_body(const float* __restrict__ X,
                                          const float* __restrict__ W,
                                          const float* __restrict__ bias,
                                          float* __restrict__ out) {
    __shared__ __align__(16) float Xs[32 * 34];  // [k][m] pad 34
    __shared__ __align__(16) float Ws[32 * 36];  // [n][k] pad 36 (float4-aligned)

    int tid = threadIdx.x;
    int m0 = blockIdx.y * 32;
    int f0 = blockIdx.x * 32;
    int lr = tid >> 1;          // load row 0..31 (X: m row, W: n row)
    int lc = (tid & 1) * 4;     // float4 col base; chunks at +8i
    int mg = tid & 7;           // m = m0 + 2mg + 16mp
    int ng = tid >> 3;          // f = f0 + ng*4 + nn

    float4 xp[4], wp[4];
#pragma unroll
    for (int i = 0; i < 4; i++) {
        xp[i] = *reinterpret_cast<const float4*>(X + (size_t)(m0 + lr) * EE + lc + 8 * i);
        wp[i] = *reinterpret_cast<const float4*>(W + (size_t)(f0 + lr) * EE + lc + 8 * i);
    }

    ull acc[2][4] = {};

    for (int kt = 0; kt < EE; kt += 32) {
        __syncthreads();
#pragma unroll
        for (int i = 0; i < 4; i++) {
            Xs[(lc + 8 * i + 0) * 34 + lr] = xp[i].x;
            Xs[(lc + 8 * i + 1) * 34 + lr] = xp[i].y;
            Xs[(lc + 8 * i + 2) * 34 + lr] = xp[i].z;
            Xs[(lc + 8 * i + 3) * 34 + lr] = xp[i].w;
            *reinterpret_cast<float4*>(&Ws[lr * 36 + lc + 8 * i]) = wp[i];
        }
        __syncthreads();
        if (kt + 32 < EE) {
#pragma unroll
            for (int i = 0; i < 4; i++) {
                xp[i] = *reinterpret_cast<const float4*>(
                    X + (size_t)(m0 + lr) * EE + kt + 32 + lc + 8 * i);
                wp[i] = *reinterpret_cast<const float4*>(
                    W + (size_t)(f0 + lr) * EE + kt + 32 + lc + 8 * i);
            }
        }
#pragma unroll
        for (int k = 0; k < 32; k++) {
            ull a0 = *reinterpret_cast<const ull*>(&Xs[k * 34 + 2 * mg]);
            ull a1 = *reinterpret_cast<const ull*>(&Xs[k * 34 + 2 * mg + 16]);
#pragma unroll
            for (int nn = 0; nn < 4; nn++) {
                ull b = dup2(Ws[(ng * 4 + nn) * 36 + k]);
                ffma2(acc[0][nn], a0, b);
                ffma2(acc[1][nn], a1, b);
            }
        }
    }

#pragma unroll
    for (int nn = 0; nn < 4; nn++) {
        int f = f0 + ng * 4 + nn;
        float bv = bias[f];
#pragma unroll
        for (int mp = 0; mp < 2; mp++) {
            int m = m0 + 2 * mg + 16 * mp;   // even
            float v0 = lo32(acc[mp][nn]) + bv;
            float v1 = hi32(acc[mp][nn]) + bv;
            if (MODE == 0) {
                out[(size_t)m * EE + f] = v0;
                out[(size_t)(m + 1) * EE + f] = v1;
            } else {
                int b = m >> 4, s = m & 15, h = f >> 7, d = f & 127;
                size_t base = (((size_t)(b * HH + h)) * SS + s) * DD + d;
                out[base] = v0;
                out[base + DD] = v1;  // s+1, same b
            }
        }
    }
}

__global__ void __launch_bounds__(64) qkv_gemm(const float* __restrict__ emb,
                                               const float* __restrict__ Wq,
                                               const float* __restrict__ Wk,
                                               const float* __restrict__ Wv,
                                               const float* __restrict__ bq,
                                               const float* __restrict__ bk,
                                               const float* __restrict__ bv,
                                               float* __restrict__ kout,
                                               float* __restrict__ vout) {
    const float* W;
    const float* bias;
    float* o;
    if (blockIdx.z == 0) { W = Wq; bias = bq; o = g_q; }
    else if (blockIdx.z == 1) { W = Wk; bias = bk; o = kout; }
    else { W = Wv; bias = bv; o = vout; }
    gemm_body<1>(emb, W, bias, o);
}

__global__ void __launch_bounds__(64) out_gemm(const float* __restrict__ Wo,
                                               const float* __restrict__ bo,
                                               float* __restrict__ out) {
    gemm_body<0>(g_ctx, Wo, bo, out);
}

// =============================================================================
// Flash attention, split-KV x2, 256 threads, 32-key tiles, 2 CTAs/SM.
// Q in SMEM (multicast reads -> no 64-reg qreg, no spills). Separate SP
// buffer; V double-buffered (the only WAR hazard) -> 3 barriers per tile.
// K+V of tile n+1 LDG'd at top of scores(n): ~2000-cycle latency cover.
// Dynamic smem layout (floats):
//   Qs @ 0      (16*132 = 2112)
//   Ks @ 2112   (32*132 = 4224)
//   V0 @ 6336   (4224)     V1 @ 10560 (4224)
//   SP @ 14784  (8*528 = 4224)          total 19008 floats = 76032 B
// Epilogue FB[256][33] aliases base (Qs+Ks+V0 head, all dead by then).
// =============================================================================
#define FL_QS   0
#define FL_KS   2112
#define FL_V0   6336
#define FL_V1   10560
#define FL_SP   14784
#define FL_TOT  19008

__global__ void __launch_bounds__(256, 2) flash_kernel(const float* __restrict__ kc,
                                                       const float* __restrict__ vc,
                                                       const float* __restrict__ knew,
                                                       const float* __restrict__ vnew) {
    extern __shared__ float SM[];
    __shared__ float Ss[16 * 34];
    __shared__ float m_s[16], l_s[16], c_s[16];

    float* Qs = SM + FL_QS;
    float* Ks = SM + FL_KS;
    float* SP = SM + FL_SP;
    float* FB = SM;

    int tid = threadIdx.x;
    int bh = blockIdx.x & 127;
    int split = blockIdx.x >> 7;

    // scores ids: 4 q-groups x 8 key-groups x 8 d-groups
    int qgA = tid & 3;
    int kgA = (tid >> 2) & 7;
    int dgA = tid >> 5;
    // PV ids
    int dg2 = tid & 15;          // d = 2*dg2 + 32*r
    int qg2 = (tid >> 4) & 3;
    int ksl = tid >> 6;          // 4 key slices x 8 keys
    // softmax ids
    int warp = tid >> 5;
    int lane = tid & 31;
    // loader ids
    int jl = tid >> 3;           // row 0..31
    int cl = tid & 7;            // float4 cols cl*4 + 32t

    // load Q (16 x 128) into smem, padded rows of 132
    {
        const float* qb = g_q + (size_t)bh * (SS * DD);
#pragma unroll
        for (int rep = 0; rep < 2; rep++) {
            int i = tid + 256 * rep;          // float4 index 0..511
            int q = (i * 4) >> 7, d = (i * 4) & 127;
            *reinterpret_cast<float4*>(&Qs[q * 132 + d]) =
                *reinterpret_cast<const float4*>(&qb[i * 4]);
        }
    }
    if (tid < 16) { m_s[tid] = -1e30f; l_s[tid] = 0.f; }

    const float scale = 0.08838834764831845f;  // 1/sqrt(128)
    const int t0 = split * 64;
    const int NT = split ? 65 : 64;  // split 1 owns the 16-key tail tile

    ull o2[4][4] = {};

    float4 kpre[4], vpre[4];
    {
        const float* ks0 = kc + ((size_t)bh * TCACHE + (size_t)t0 * 32) * DD;
        const float* vs0 = vc + ((size_t)bh * TCACHE + (size_t)t0 * 32) * DD;
#pragma unroll
        for (int t = 0; t < 4; t++) {
            kpre[t] = *reinterpret_cast<const float4*>(ks0 + (size_t)jl * DD + cl * 4 + 32 * t);
            vpre[t] = *reinterpret_cast<const float4*>(vs0 + (size_t)jl * DD + cl * 4 + 32 * t);
        }
    }

    for (int lt = 0; lt < NT; lt++) {
        int tile = t0 + lt;
        bool tail = (tile == 128);
        bool on = !tail || (jl < 16);
        float* Vw = SM + ((lt & 1) ? FL_V1 : FL_V0);

        // STS K and V (prefetched registers)
        if (on) {
#pragma unroll
            for (int t = 0; t < 4; t++) {
                *reinterpret_cast<float4*>(&Ks[jl * 132 + cl * 4 + 32 * t]) = kpre[t];
                *reinterpret_cast<float4*>(&Vw[jl * 132 + cl * 4 + 32 * t]) = vpre[t];
            }
        }
        __syncthreads();  // (a) K,V visible; Qs ready on first iter

        // LDG next tile's K and V (land during scores+softmax)
        if (lt + 1 < NT) {
            int tn = tile + 1;
            bool ntail = (tn == 128);
            const float* ksrc = !ntail
                ? kc + ((size_t)bh * TCACHE + (size_t)tn * 32) * DD
                : knew + (size_t)bh * (SS * DD);
            const float* vsrc = !ntail
                ? vc + ((size_t)bh * TCACHE + (size_t)tn * 32) * DD
                : vnew + (size_t)bh * (SS * DD);
            if (!ntail || jl < 16) {
#pragma unroll
                for (int t = 0; t < 4; t++) {
                    kpre[t] = *reinterpret_cast<const float4*>(
                        ksrc + (size_t)jl * DD + cl * 4 + 32 * t);
                    vpre[t] = *reinterpret_cast<const float4*>(
                        vsrc + (size_t)jl * DD + cl * 4 + 32 * t);
                }
            }
        }

        // scores: acc[qq][kk], 16 d's per thread; Q via multicast LDS
        {
            ull acc[4][4] = {};
#pragma unroll
            for (int dp = 0; dp < 8; dp++) {
                ull qv[4];
#pragma unroll
                for (int qq = 0; qq < 4; qq++)
                    qv[qq] = *reinterpret_cast<const ull*>(
                        &Qs[(qgA * 4 + qq) * 132 + dgA * 16 + 2 * dp]);
#pragma unroll
                for (int kk = 0; kk < 4; kk++) {
                    ull kv = *reinterpret_cast<const ull*>(
                        &Ks[(kgA + 8 * kk) * 132 + dgA * 16 + 2 * dp]);
#pragma unroll
                    for (int qq = 0; qq < 4; qq++)
                        ffma2(acc[qq][kk], qv[qq], kv);
                }
            }
#pragma unroll
            for (int qq = 0; qq < 4; qq++)
#pragma unroll
                for (int kk = 0; kk < 4; kk++)
                    SP[dgA * 528 + (qgA * 4 + qq) * 33 + (kgA + 8 * kk)] =
                        lo32(acc[qq][kk]) + hi32(acc[qq][kk]);
        }
        __syncthreads();  // (b) SP complete

        // fused reduce + online softmax: warp w owns rows w and w+8, lane = k
#pragma unroll
        for (int rr = 0; rr < 2; rr++) {
            int row = warp + 8 * rr;
            float s = 0.f;
#pragma unroll
            for (int dg = 0; dg < 8; dg++) s += SP[dg * 528 + row * 33 + lane];
            s *= scale;
            if (tail && lane > row) s = -1e30f;  // also kills stale k>=16 slots
            float mx = s;
#pragma unroll
            for (int off = 16; off; off >>= 1)
                mx = fmaxf(mx, __shfl_xor_sync(0xffffffffu, mx, off));
            float mold = m_s[row];
            float mnew = fmaxf(mold, mx);
            float p = __expf(s - mnew);
            Ss[row * 34 + lane] = p;
            float sum = p;
#pragma unroll
            for (int off = 16; off; off >>= 1)
                sum += __shfl_xor_sync(0xffffffffu, sum, off);
            if (lane == 0) {
                float c = __expf(mold - mnew);
                m_s[row] = mnew;
                l_s[row] = l_s[row] * c + sum;
                c_s[row] = c;
            }
        }
        __syncthreads();  // (c) Ss/c_s ready, SP consumed

        // PV: o = o*c + P @ V from this tile's V buffer
        {
            ull cf[4];
#pragma unroll
            for (int qq = 0; qq < 4; qq++) cf[qq] = dup2(c_s[qg2 * 4 + qq]);
#pragma unroll
            for (int qq = 0; qq < 4; qq++)
#pragma unroll
                for (int r = 0; r < 4; r++) fmul2(o2[qq][r], cf[qq]);

#pragma unroll
            for (int jj = 0; jj < 8; jj++) {
                int j = ksl * 8 + jj;
                ull pf[4];
#pragma unroll
                for (int qq = 0; qq < 4; qq++)
                    pf[qq] = dup2(Ss[(qg2 * 4 + qq) * 34 + j]);
#pragma unroll
                for (int r = 0; r < 4; r++) {
                    ull vv = *reinterpret_cast<const ull*>(
                        &Vw[j * 132 + 2 * dg2 + 32 * r]);
#pragma unroll
                    for (int qq = 0; qq < 4; qq++) ffma2(o2[qq][r], pf[qq], vv);
                }
            }
        }
    }

    // epilogue: store (m,l); reduce 4 key-slice partials; write unnormalized
    __syncthreads();
    if (tid < 16) {
        g_ml[((size_t)(split * 128 + bh) * 16 + tid) * 2 + 0] = m_s[tid];
        g_ml[((size_t)(split * 128 + bh) * 16 + tid) * 2 + 1] = l_s[tid];
    }
#pragma unroll
    for (int qq = 0; qq < 4; qq++)
#pragma unroll
        for (int r = 0; r < 4; r++) {
            FB[tid * 33 + qq * 8 + r * 2]     = lo32(o2[qq][r]);
            FB[tid * 33 + qq * 8 + r * 2 + 1] = hi32(o2[qq][r]);
        }
    __syncthreads();
    if (tid < 64) {
        float* dst = g_part + ((size_t)(split * 128 + bh)) * (SS * DD);
#pragma unroll
        for (int i = 0; i < 32; i++) {
            float v = FB[tid * 33 + i] + FB[(tid + 64) * 33 + i] +
                      FB[(tid + 128) * 33 + i] + FB[(tid + 192) * 33 + i];
            int qq = i >> 3, r = (i >> 1) & 3, lh = i & 1;
            int q = qg2 * 4 + qq;
            int d = 2 * dg2 + 32 * r + lh;
            dst[q * DD + d] = v;
        }
    }
}

// =============================================================================
// Combine splits: o = (o0*e^(m0-M) + o1*e^(m1-M)) / (l0*e0 + l1*e1)
// =============================================================================
__global__ void __launch_bounds__(256) combine_kernel() {
    __shared__ float w0s[16], w1s[16];
    int bh = blockIdx.x;
    int tid = threadIdx.x;
    if (tid < 16) {
        float m0 = g_ml[((size_t)bh * 16 + tid) * 2 + 0];
        float l0 = g_ml[((size_t)bh * 16 + tid) * 2 + 1];
        float m1 = g_ml[((size_t)(128 + bh) * 16 + tid) * 2 + 0];
        float l1 = g_ml[((size_t)(128 + bh) * 16 + tid) * 2 + 1];
        float M = fmaxf(m0, m1);
        float e0 = __expf(m0 - M), e1 = __expf(m1 - M);
        float inv = 1.f / (l0 * e0 + l1 * e1);
        w0s[tid] = e0 * inv;
        w1s[tid] = e1 * inv;
    }
    __syncthreads();
    int b = bh >> 4, h = bh & 15;
    const float* p0 = g_part + (size_t)bh * (SS * DD);
    const float* p1 = g_part + (size_t)(128 + bh) * (SS * DD);
    for (int idx = tid; idx < SS * DD; idx += 256) {
        int q = idx >> 7;
        g_ctx[((size_t)(b * SS + q)) * EE + h * DD + (idx & 127)] =
            p0[idx] * w0s[q] + p1[idx] * w1s[q];
    }
}

// ---------------- launch -----------------------------------------------------
extern "C" void kernel_launch(void* const* d_in, const int* in_sizes, int n_in,
                              void* d_out, int out_size) {
    const float* emb = (const float*)d_in[0];
    const float* kc  = (const float*)d_in[1];
    const float* vc  = (const float*)d_in[2];
    const float* Wq  = (const float*)d_in[3];
    const float* bq  = (const float*)d_in[4];
    const float* Wk  = (const float*)d_in[5];
    const float* bk  = (const float*)d_in[6];
    const float* Wv  = (const float*)d_in[7];
    const float* bv  = (const float*)d_in[8];
    const float* Wo  = (const float*)d_in[9];
    const float* bo  = (const float*)d_in[10];

    float* out  = (float*)d_out;          // (8,16,2048)
    float* kout = out + MM * EE;          // k_new (8,16,16,128)
    float* vout = out + 2 * MM * EE;      // v_new (8,16,16,128)

    (void)cudaFuncSetAttribute(flash_kernel,
                               cudaFuncAttributeMaxDynamicSharedMemorySize,
                               FL_TOT * (int)sizeof(float));

    qkv_gemm<<<dim3(64, 4, 3), 64>>>(emb, Wq, Wk, Wv, bq, bk, bv, kout, vout);
    flash_kernel<<<256, 256, FL_TOT * sizeof(float)>>>(kc, vc, kout, vout);
    combine_kernel<<<128, 256>>>();
    out_gemm<<<dim3(64, 4), 64>>>(Wo, bo, out);
}

// round 15
// speedup vs baseline: 1.1067x; 1.0133x over previous
#include <cuda_runtime.h>
#include <math.h>

#define BB 8
#define SS 16
#define HH 16
#define DD 128
#define EE 2048
#define MM 128          // B*S rows
#define TCACHE 4096

typedef unsigned long long ull;

// ---------------- scratch (device globals) ----------------------------------
__device__ float g_q[MM * EE];                // (b,h,s,d)
__device__ float g_ctx[MM * EE];              // (b,s,e)
__device__ float g_part[2 * 128 * 16 * 128];  // [split][bh][q][d] unnormalized
__device__ float g_ml[2 * 128 * 16 * 2];      // [split][bh][q][{m,l}]

// ---------------- f32x2 helpers ---------------------------------------------
__device__ __forceinline__ void ffma2(ull& d, ull a, ull b) {
    asm("fma.rn.f32x2 %0, %1, %2, %0;" : "+l"(d) : "l"(a), "l"(b));
}
__device__ __forceinline__ void fmul2(ull& d, ull b) {
    asm("mul.rn.f32x2 %0, %0, %1;" : "+l"(d) : "l"(b));
}
__device__ __forceinline__ ull pack2(float a, float b) {
    ull r;
    asm("mov.b64 %0, {%1, %2};" : "=l"(r) : "f"(a), "f"(b));
    return r;
}
__device__ __forceinline__ ull dup2(float x) { return pack2(x, x); }
__device__ __forceinline__ float lo32(ull v) {
    return __uint_as_float((unsigned)(v & 0xffffffffull));
}
__device__ __forceinline__ float hi32(ull v) {
    return __uint_as_float((unsigned)(v >> 32));
}

// ---------------- cp.async helpers ------------------------------------------
__device__ __forceinline__ void cp16(float* smem_dst, const float* gsrc) {
    unsigned s = (unsigned)__cvta_generic_to_shared(smem_dst);
    asm volatile("cp.async.cg.shared.global [%0], [%1], 16;"
                 :: "r"(s), "l"(gsrc));
}
__device__ __forceinline__ void cp_commit() {
    asm volatile("cp.async.commit_group;");
}
__device__ __forceinline__ void cp_wait0() {
    asm volatile("cp.async.wait_group 0;" ::: "memory");
}

// =============================================================================
// GEMM body: 32x32 tile, BK=32, 64 threads. Thread tile 4m(2 f32x2 pairs)x4n.
// (unchanged from the 465-us passing version)
// MODE 0: out[m*2048+f];  MODE 1: out[((b*16+h)*16+s)*128+d]
// =============================================================================
template <int MODE>
__device__ __forceinline__ void gemm_body(const float* __restrict__ X,
                                          const float* __restrict__ W,
                                          const float* __restrict__ bias,
                                          float* __restrict__ out) {
    __shared__ __align__(16) float Xs[32 * 34];  // [k][m] pad 34
    __shared__ __align__(16) float Ws[32 * 36];  // [n][k] pad 36

    int tid = threadIdx.x;
    int m0 = blockIdx.y * 32;
    int f0 = blockIdx.x * 32;
    int lr = tid >> 1;          // load row 0..31
    int lc = (tid & 1) * 4;     // float4 col base; chunks at +8i
    int mg = tid & 7;           // m = m0 + 2mg + 16mp
    int ng = tid >> 3;          // f = f0 + ng*4 + nn

    float4 xp[4], wp[4];
#pragma unroll
    for (int i = 0; i < 4; i++) {
        xp[i] = *reinterpret_cast<const float4*>(X + (size_t)(m0 + lr) * EE + lc + 8 * i);
        wp[i] = *reinterpret_cast<const float4*>(W + (size_t)(f0 + lr) * EE + lc + 8 * i);
    }

    ull acc[2][4] = {};

    for (int kt = 0; kt < EE; kt += 32) {
        __syncthreads();
#pragma unroll
        for (int i = 0; i < 4; i++) {
            Xs[(lc + 8 * i + 0) * 34 + lr] = xp[i].x;
            Xs[(lc + 8 * i + 1) * 34 + lr] = xp[i].y;
            Xs[(lc + 8 * i + 2) * 34 + lr] = xp[i].z;
            Xs[(lc + 8 * i + 3) * 34 + lr] = xp[i].w;
            *reinterpret_cast<float4*>(&Ws[lr * 36 + lc + 8 * i]) = wp[i];
        }
        __syncthreads();
        if (kt + 32 < EE) {
#pragma unroll
            for (int i = 0; i < 4; i++) {
                xp[i] = *reinterpret_cast<const float4*>(
                    X + (size_t)(m0 + lr) * EE + kt + 32 + lc + 8 * i);
                wp[i] = *reinterpret_cast<const float4*>(
                    W + (size_t)(f0 + lr) * EE + kt + 32 + lc + 8 * i);
            }
        }
#pragma unroll
        for (int k = 0; k < 32; k++) {
            ull a0 = *reinterpret_cast<const ull*>(&Xs[k * 34 + 2 * mg]);
            ull a1 = *reinterpret_cast<const ull*>(&Xs[k * 34 + 2 * mg + 16]);
#pragma unroll
            for (int nn = 0; nn < 4; nn++) {
                ull b = dup2(Ws[(ng * 4 + nn) * 36 + k]);
                ffma2(acc[0][nn], a0, b);
                ffma2(acc[1][nn], a1, b);
            }
        }
    }

#pragma unroll
    for (int nn = 0; nn < 4; nn++) {
        int f = f0 + ng * 4 + nn;
        float bv = bias[f];
#pragma unroll
        for (int mp = 0; mp < 2; mp++) {
            int m = m0 + 2 * mg + 16 * mp;   // even
            float v0 = lo32(acc[mp][nn]) + bv;
            float v1 = hi32(acc[mp][nn]) + bv;
            if (MODE == 0) {
                out[(size_t)m * EE + f] = v0;
                out[(size_t)(m + 1) * EE + f] = v1;
            } else {
                int b = m >> 4, s = m & 15, h = f >> 7, d = f & 127;
                size_t base = (((size_t)(b * HH + h)) * SS + s) * DD + d;
                out[base] = v0;
                out[base + DD] = v1;  // s+1, same b
            }
        }
    }
}

__global__ void __launch_bounds__(64) qkv_gemm(const float* __restrict__ emb,
                                               const float* __restrict__ Wq,
                                               const float* __restrict__ Wk,
                                               const float* __restrict__ Wv,
                                               const float* __restrict__ bq,
                                               const float* __restrict__ bk,
                                               const float* __restrict__ bv,
                                               float* __restrict__ kout,
                                               float* __restrict__ vout) {
    const float* W;
    const float* bias;
    float* o;
    if (blockIdx.z == 0) { W = Wq; bias = bq; o = g_q; }
    else if (blockIdx.z == 1) { W = Wk; bias = bk; o = kout; }
    else { W = Wv; bias = bv; o = vout; }
    gemm_body<1>(emb, W, bias, o);
}

__global__ void __launch_bounds__(64) out_gemm(const float* __restrict__ Wo,
                                               const float* __restrict__ bo,
                                               float* __restrict__ out) {
    gemm_body<0>(g_ctx, Wo, bo, out);
}

// =============================================================================
// Flash attention, split-KV x2, 256 threads, 32-key tiles, 2 CTAs/SM.
// K/V staged via cp.async (LDGSTS): no prefetch registers, no STS, one group
// in flight covering the next tile during the current tile's compute.
// Dynamic smem layout (floats):
//   Qs @ 0      (16*132 = 2112)
//   K0 @ 2112   (32*132 = 4224)    K1 @ 6336
//   V0 @ 10560  (4224)             V1 @ 14784
//   SP @ 19008  (8*528 = 4224)     total 23232 floats = 92928 B
// Epilogue FB[256][33] aliases base (Qs+K0+K1 head, all dead by then).
// =============================================================================
#define FL_QS   0
#define FL_K0   2112
#define FL_K1   6336
#define FL_V0   10560
#define FL_V1   14784
#define FL_SP   19008
#define FL_TOT  23232

__global__ void __launch_bounds__(256, 2) flash_kernel(const float* __restrict__ kc,
                                                       const float* __restrict__ vc,
                                                       const float* __restrict__ knew,
                                                       const float* __restrict__ vnew) {
    extern __shared__ float SM[];
    __shared__ float Ss[16 * 34];
    __shared__ float m_s[16], l_s[16], c_s[16];

    float* Qs = SM + FL_QS;
    float* SP = SM + FL_SP;
    float* FB = SM;

    int tid = threadIdx.x;
    int bh = blockIdx.x & 127;
    int split = blockIdx.x >> 7;

    // scores ids: 4 q-groups x 8 key-groups x 8 d-groups
    int qgA = tid & 3;
    int kgA = (tid >> 2) & 7;
    int dgA = tid >> 5;
    // PV ids
    int dg2 = tid & 15;          // d = 2*dg2 + 32*r
    int qg2 = (tid >> 4) & 3;
    int ksl = tid >> 6;          // 4 key slices x 8 keys
    // softmax ids
    int warp = tid >> 5;
    int lane = tid & 31;
    // loader ids
    int jl = tid >> 3;           // row 0..31
    int cl = tid & 7;            // 16B chunks at float cols cl*4 + 32t

    // cp.async issue of one K/V tile into buffer `buf`
    auto issue_kv = [&](int tile, int buf) {
        bool tl = (tile == 128);
        const float* ksrc = !tl
            ? kc + ((size_t)bh * TCACHE + (size_t)tile * 32) * DD
            : knew + (size_t)bh * (SS * DD);
        const float* vsrc = !tl
            ? vc + ((size_t)bh * TCACHE + (size_t)tile * 32) * DD
            : vnew + (size_t)bh * (SS * DD);
        if (!tl || jl < 16) {
            float* Kd = SM + (buf ? FL_K1 : FL_K0) + jl * 132 + cl * 4;
            float* Vd = SM + (buf ? FL_V1 : FL_V0) + jl * 132 + cl * 4;
            const float* kg = ksrc + (size_t)jl * DD + cl * 4;
            const float* vg = vsrc + (size_t)jl * DD + cl * 4;
#pragma unroll
            for (int t = 0; t < 4; t++) {
                cp16(Kd + 32 * t, kg + 32 * t);
                cp16(Vd + 32 * t, vg + 32 * t);
            }
        }
    };

    // load Q (16 x 128) into smem, padded rows of 132
    {
        const float* qb = g_q + (size_t)bh * (SS * DD);
#pragma unroll
        for (int rep = 0; rep < 2; rep++) {
            int i = tid + 256 * rep;          // float4 index 0..511
            int q = (i * 4) >> 7, d = (i * 4) & 127;
            *reinterpret_cast<float4*>(&Qs[q * 132 + d]) =
                *reinterpret_cast<const float4*>(&qb[i * 4]);
        }
    }
    if (tid < 16) { m_s[tid] = -1e30f; l_s[tid] = 0.f; }

    const float scale = 0.08838834764831845f;  // 1/sqrt(128)
    const int t0 = split * 64;
    const int NT = split ? 65 : 64;  // split 1 owns the 16-key tail tile

    ull o2[4][4] = {};

    // prologue: stage tile t0 into buffer 0
    issue_kv(t0, 0);
    cp_commit();

    for (int lt = 0; lt < NT; lt++) {
        int tile = t0 + lt;
        bool tail = (tile == 128);
        int cur = lt & 1;
        float* Ks = SM + (cur ? FL_K1 : FL_K0);
        float* Vw = SM + (cur ? FL_V1 : FL_V0);

        cp_wait0();       // this tile's K/V landed (own chunks)
        __syncthreads();  // (a) all threads past prior PV; K/V/Qs visible

        // stage next tile into the alternate buffers (dead since barrier a)
        if (lt + 1 < NT) {
            issue_kv(tile + 1, cur ^ 1);
        }
        cp_commit();      // uniform group count every iteration

        // scores: acc[qq][kk], 16 d's per thread; Q via multicast LDS
        {
            ull acc[4][4] = {};
#pragma unroll
            for (int dp = 0; dp < 8; dp++) {
                ull qv[4];
#pragma unroll
                for (int qq = 0; qq < 4; qq++)
                    qv[qq] = *reinterpret_cast<const ull*>(
                        &Qs[(qgA * 4 + qq) * 132 + dgA * 16 + 2 * dp]);
#pragma unroll
                for (int kk = 0; kk < 4; kk++) {
                    ull kv = *reinterpret_cast<const ull*>(
                        &Ks[(kgA + 8 * kk) * 132 + dgA * 16 + 2 * dp]);
#pragma unroll
                    for (int qq = 0; qq < 4; qq++)
                        ffma2(acc[qq][kk], qv[qq], kv);
                }
            }
#pragma unroll
            for (int qq = 0; qq < 4; qq++)
#pragma unroll
                for (int kk = 0; kk < 4; kk++)
                    SP[dgA * 528 + (qgA * 4 + qq) * 33 + (kgA + 8 * kk)] =
                        lo32(acc[qq][kk]) + hi32(acc[qq][kk]);
        }
        __syncthreads();  // (b) SP complete

        // fused reduce + online softmax: warp w owns rows w and w+8, lane = k
#pragma unroll
        for (int rr = 0; rr < 2; rr++) {
            int row = warp + 8 * rr;
            float s = 0.f;
#pragma unroll
            for (int dg = 0; dg < 8; dg++) s += SP[dg * 528 + row * 33 + lane];
            s *= scale;
            if (tail && lane > row) s = -1e30f;  // also kills stale k>=16 slots
            float mx = s;
#pragma unroll
            for (int off = 16; off; off >>= 1)
                mx = fmaxf(mx, __shfl_xor_sync(0xffffffffu, mx, off));
            float mold = m_s[row];
            float mnew = fmaxf(mold, mx);
            float p = __expf(s - mnew);
            Ss[row * 34 + lane] = p;
            float sum = p;
#pragma unroll
            for (int off = 16; off; off >>= 1)
                sum += __shfl_xor_sync(0xffffffffu, sum, off);
            if (lane == 0) {
                float c = __expf(mold - mnew);
                m_s[row] = mnew;
                l_s[row] = l_s[row] * c + sum;
                c_s[row] = c;
            }
        }
        __syncthreads();  // (c) Ss/c_s ready, SP consumed

        // PV: o = o*c + P @ V from this tile's V buffer
        {
            ull cf[4];
#pragma unroll
            for (int qq = 0; qq < 4; qq++) cf[qq] = dup2(c_s[qg2 * 4 + qq]);
#pragma unroll
            for (int qq = 0; qq < 4; qq++)
#pragma unroll
                for (int r = 0; r < 4; r++) fmul2(o2[qq][r], cf[qq]);

#pragma unroll
            for (int jj = 0; jj < 8; jj++) {
                int j = ksl * 8 + jj;
                ull pf[4];
#pragma unroll
                for (int qq = 0; qq < 4; qq++)
                    pf[qq] = dup2(Ss[(qg2 * 4 + qq) * 34 + j]);
#pragma unroll
                for (int r = 0; r < 4; r++) {
                    ull vv = *reinterpret_cast<const ull*>(
                        &Vw[j * 132 + 2 * dg2 + 32 * r]);
#pragma unroll
                    for (int qq = 0; qq < 4; qq++) ffma2(o2[qq][r], pf[qq], vv);
                }
            }
        }
    }

    // epilogue: store (m,l); reduce 4 key-slice partials; write unnormalized
    __syncthreads();
    if (tid < 16) {
        g_ml[((size_t)(split * 128 + bh) * 16 + tid) * 2 + 0] = m_s[tid];
        g_ml[((size_t)(split * 128 + bh) * 16 + tid) * 2 + 1] = l_s[tid];
    }
#pragma unroll
    for (int qq = 0; qq < 4; qq++)
#pragma unroll
        for (int r = 0; r < 4; r++) {
            FB[tid * 33 + qq * 8 + r * 2]     = lo32(o2[qq][r]);
            FB[tid * 33 + qq * 8 + r * 2 + 1] = hi32(o2[qq][r]);
        }
    __syncthreads();
    if (tid < 64) {
        float* dst = g_part + ((size_t)(split * 128 + bh)) * (SS * DD);
#pragma unroll
        for (int i = 0; i < 32; i++) {
            float v = FB[tid * 33 + i] + FB[(tid + 64) * 33 + i] +
                      FB[(tid + 128) * 33 + i] + FB[(tid + 192) * 33 + i];
            int qq = i >> 3, r = (i >> 1) & 3, lh = i & 1;
            int q = qg2 * 4 + qq;
            int d = 2 * dg2 + 32 * r + lh;
            dst[q * DD + d] = v;
        }
    }
}

// =============================================================================
// Combine splits: o = (o0*e^(m0-M) + o1*e^(m1-M)) / (l0*e0 + l1*e1)
// =============================================================================
__global__ void __launch_bounds__(256) combine_kernel() {
    __shared__ float w0s[16], w1s[16];
    int bh = blockIdx.x;
    int tid = threadIdx.x;
    if (tid < 16) {
        float m0 = g_ml[((size_t)bh * 16 + tid) * 2 + 0];
        float l0 = g_ml[((size_t)bh * 16 + tid) * 2 + 1];
        float m1 = g_ml[((size_t)(128 + bh) * 16 + tid) * 2 + 0];
        float l1 = g_ml[((size_t)(128 + bh) * 16 + tid) * 2 + 1];
        float M = fmaxf(m0, m1);
        float e0 = __expf(m0 - M), e1 = __expf(m1 - M);
        float inv = 1.f / (l0 * e0 + l1 * e1);
        w0s[tid] = e0 * inv;
        w1s[tid] = e1 * inv;
    }
    __syncthreads();
    int b = bh >> 4, h = bh & 15;
    const float* p0 = g_part + (size_t)bh * (SS * DD);
    const float* p1 = g_part + (size_t)(128 + bh) * (SS * DD);
    for (int idx = tid; idx < SS * DD; idx += 256) {
        int q = idx >> 7;
        g_ctx[((size_t)(b * SS + q)) * EE + h * DD + (idx & 127)] =
            p0[idx] * w0s[q] + p1[idx] * w1s[q];
    }
}

// ---------------- launch -----------------------------------------------------
extern "C" void kernel_launch(void* const* d_in, const int* in_sizes, int n_in,
                              void* d_out, int out_size) {
    const float* emb = (const float*)d_in[0];
    const float* kc  = (const float*)d_in[1];
    const float* vc  = (const float*)d_in[2];
    const float* Wq  = (const float*)d_in[3];
    const float* bq  = (const float*)d_in[4];
    const float* Wk  = (const float*)d_in[5];
    const float* bk  = (const float*)d_in[6];
    const float* Wv  = (const float*)d_in[7];
    const float* bv  = (const float*)d_in[8];
    const float* Wo  = (const float*)d_in[9];
    const float* bo  = (const float*)d_in[10];

    float* out  = (float*)d_out;          // (8,16,2048)
    float* kout = out + MM * EE;          // k_new (8,16,16,128)
    float* vout = out + 2 * MM * EE;      // v_new (8,16,16,128)

    (void)cudaFuncSetAttribute(flash_kernel,
                               cudaFuncAttributeMaxDynamicSharedMemorySize,
                               FL_TOT * (int)sizeof(float));

    qkv_gemm<<<dim3(64, 4, 3), 64>>>(emb, Wq, Wk, Wv, bq, bk, bv, kout, vout);
    flash_kernel<<<256, 256, FL_TOT * sizeof(float)>>>(kc, vc, kout, vout);
    combine_kernel<<<128, 256>>>();
    out_gemm<<<dim3(64, 4), 64>>>(Wo, bo, out);
}

// round 16
// speedup vs baseline: 1.3628x; 1.2314x over previous
#include <cuda_runtime.h>
#include <math.h>

#define BB 8
#define SS 16
#define HH 16
#define DD 128
#define EE 2048
#define MM 128          // B*S rows
#define TCACHE 4096

typedef unsigned long long ull;

// ---------------- scratch (device globals) ----------------------------------
__device__ float g_q[MM * EE];                // (b,h,s,d)
__device__ float g_ctx[MM * EE];              // (b,s,e)
__device__ float g_part[2 * 128 * 16 * 128];  // [split][bh][q][d] unnormalized
__device__ float g_ml[2 * 128 * 16 * 2];      // [split][bh][q][{m,l}]

// ---------------- f32x2 helpers ---------------------------------------------
__device__ __forceinline__ void ffma2(ull& d, ull a, ull b) {
    asm("fma.rn.f32x2 %0, %1, %2, %0;" : "+l"(d) : "l"(a), "l"(b));
}
__device__ __forceinline__ void fmul2(ull& d, ull b) {
    asm("mul.rn.f32x2 %0, %0, %1;" : "+l"(d) : "l"(b));
}
__device__ __forceinline__ ull pack2(float a, float b) {
    ull r;
    asm("mov.b64 %0, {%1, %2};" : "=l"(r) : "f"(a), "f"(b));
    return r;
}
__device__ __forceinline__ ull dup2(float x) { return pack2(x, x); }
__device__ __forceinline__ float lo32(ull v) {
    return __uint_as_float((unsigned)(v & 0xffffffffull));
}
__device__ __forceinline__ float hi32(ull v) {
    return __uint_as_float((unsigned)(v >> 32));
}

// ---------------- cp.async helpers ------------------------------------------
__device__ __forceinline__ void cp16(float* smem_dst, const float* gsrc) {
    unsigned s = (unsigned)__cvta_generic_to_shared(smem_dst);
    asm volatile("cp.async.cg.shared.global [%0], [%1], 16;"
                 :: "r"(s), "l"(gsrc));
}
__device__ __forceinline__ void cp_commit() {
    asm volatile("cp.async.commit_group;");
}
__device__ __forceinline__ void cp_wait0() {
    asm volatile("cp.async.wait_group 0;" ::: "memory");
}

// ---------------- bf16 split + mma helpers -----------------------------------
// pack (x0 -> low half, x1 -> high half) as bf16x2; lo = residual after hi.
__device__ __forceinline__ void cvt_split(float x0, float x1,
                                          unsigned& hi, unsigned& lo) {
    asm("cvt.rn.bf16x2.f32 %0, %1, %2;" : "=r"(hi) : "f"(x1), "f"(x0));
    float h0 = __uint_as_float(hi << 16);
    float h1 = __uint_as_float(hi & 0xffff0000u);
    float l0 = x0 - h0;
    float l1 = x1 - h1;
    asm("cvt.rn.bf16x2.f32 %0, %1, %2;" : "=r"(lo) : "f"(l1), "f"(l0));
}

__device__ __forceinline__ void mma16816(float* c,
                                         unsigned a0, unsigned a1,
                                         unsigned a2, unsigned a3,
                                         unsigned b0, unsigned b1) {
    asm("mma.sync.aligned.m16n8k16.row.col.f32.bf16.bf16.f32 "
        "{%0,%1,%2,%3}, {%4,%5,%6,%7}, {%8,%9}, {%0,%1,%2,%3};"
        : "+f"(c[0]), "+f"(c[1]), "+f"(c[2]), "+f"(c[3])
        : "r"(a0), "r"(a1), "r"(a2), "r"(a3), "r"(b0), "r"(b1));
}

__device__ __forceinline__ unsigned ldsu(const unsigned short* p, int soff) {
    return *reinterpret_cast<const unsigned*>(p + soff);
}
__device__ __forceinline__ void stsu(unsigned short* p, int soff, unsigned v) {
    *reinterpret_cast<unsigned*>(p + soff) = v;
}

// =============================================================================
// Split-bf16 tensor-core GEMM: Y = X @ W^T + b via mma.sync m16n8k16.
// CTA tile (WM*32)m x 64n, BK=32, 256 threads (8 warps as 2m x 4n grid;
// each warp: WM m-tiles x 2 n-tiles). x = xhi + xlo (bf16 each); product
// = AhiBhi + AloBhi + AhiBlo, fp32 accumulate -> rel err ~2e-5.
// Smem rows padded to 40 shorts => 20-word stride => conflict-free fragment
// loads for all (g, q) lane patterns.
// MODE 0: out[m*2048+f];  MODE 1: out[((b*16+h)*16+s)*128+d]
// =============================================================================
template <int WM, int MODE>
__device__ __forceinline__ void mma_gemm(const float* __restrict__ X,
                                         const float* __restrict__ W,
                                         const float* __restrict__ bias,
                                         float* __restrict__ out) {
    constexpr int MROWS = WM * 32;
    __shared__ __align__(16) unsigned short Xhi[MROWS * 40];
    __shared__ __align__(16) unsigned short Xlo[MROWS * 40];
    __shared__ __align__(16) unsigned short Whi[64 * 40];
    __shared__ __align__(16) unsigned short Wlo[64 * 40];

    const int tid = threadIdx.x;
    const int m0 = blockIdx.y * MROWS;
    const int f0 = blockIdx.x * 64;
    const int w = tid >> 5, lane = tid & 31, g = lane >> 2, q = lane & 3;
    const int wm = w >> 2, wn = w & 3;

    // loader ids: W rows 64, 8 floats each; X rows MROWS
    const int lrw = tid >> 2, lsw = tid & 3;                  // W: row, col slot*8
    const int lrx = (WM == 2) ? lrw : (tid >> 3);
    const int lcx = (WM == 2) ? lsw * 8 : (tid & 7) * 4;

    const float* Wp = W + (size_t)(f0 + lrw) * EE + lsw * 8;  // k=0 base
    const float* Xp = X + (size_t)(m0 + lrx) * EE + lcx;

    float4 wreg[2], xreg[2];
    wreg[0] = *reinterpret_cast<const float4*>(Wp);
    wreg[1] = *reinterpret_cast<const float4*>(Wp + 4);
    xreg[0] = *reinterpret_cast<const float4*>(Xp);
    if constexpr (WM == 2) xreg[1] = *reinterpret_cast<const float4*>(Xp + 4);

    float acc[WM][2][4];
#pragma unroll
    for (int i = 0; i < WM; i++)
#pragma unroll
        for (int j = 0; j < 2; j++)
#pragma unroll
            for (int r = 0; r < 4; r++) acc[i][j][r] = 0.f;

    for (int kt = 0; kt < EE; kt += 32) {
        __syncthreads();
        {
            unsigned hi, lo;
            int so = lrw * 40 + lsw * 8;
            cvt_split(wreg[0].x, wreg[0].y, hi, lo); stsu(Whi, so,     hi); stsu(Wlo, so,     lo);
            cvt_split(wreg[0].z, wreg[0].w, hi, lo); stsu(Whi, so + 2, hi); stsu(Wlo, so + 2, lo);
            cvt_split(wreg[1].x, wreg[1].y, hi, lo); stsu(Whi, so + 4, hi); stsu(Wlo, so + 4, lo);
            cvt_split(wreg[1].z, wreg[1].w, hi, lo); stsu(Whi, so + 6, hi); stsu(Wlo, so + 6, lo);
            int sx = lrx * 40 + lcx;
            cvt_split(xreg[0].x, xreg[0].y, hi, lo); stsu(Xhi, sx,     hi); stsu(Xlo, sx,     lo);
            cvt_split(xreg[0].z, xreg[0].w, hi, lo); stsu(Xhi, sx + 2, hi); stsu(Xlo, sx + 2, lo);
            if constexpr (WM == 2) {
                cvt_split(xreg[1].x, xreg[1].y, hi, lo); stsu(Xhi, sx + 4, hi); stsu(Xlo, sx + 4, lo);
                cvt_split(xreg[1].z, xreg[1].w, hi, lo); stsu(Xhi, sx + 6, hi); stsu(Xlo, sx + 6, lo);
            }
        }
        __syncthreads();
        if (kt + 32 < EE) {
            wreg[0] = *reinterpret_cast<const float4*>(Wp + kt + 32);
            wreg[1] = *reinterpret_cast<const float4*>(Wp + kt + 36);
            xreg[0] = *reinterpret_cast<const float4*>(Xp + kt + 32);
            if constexpr (WM == 2)
                xreg[1] = *reinterpret_cast<const float4*>(Xp + kt + 36);
        }
#pragma unroll
        for (int ks = 0; ks < 2; ks++) {
            unsigned bh[2][2], bl[2][2];
#pragma unroll
            for (int j = 0; j < 2; j++) {
                int so = ((wn * 2 + j) * 8 + g) * 40 + 2 * q + 16 * ks;
                bh[j][0] = ldsu(Whi, so); bh[j][1] = ldsu(Whi, so + 8);
                bl[j][0] = ldsu(Wlo, so); bl[j][1] = ldsu(Wlo, so + 8);
            }
#pragma unroll
            for (int i = 0; i < WM; i++) {
                int so = ((wm * WM + i) * 16 + g) * 40 + 2 * q + 16 * ks;
                unsigned ah0 = ldsu(Xhi, so),     ah1 = ldsu(Xhi, so + 320);
                unsigned ah2 = ldsu(Xhi, so + 8), ah3 = ldsu(Xhi, so + 328);
                unsigned al0 = ldsu(Xlo, so),     al1 = ldsu(Xlo, so + 320);
                unsigned al2 = ldsu(Xlo, so + 8), al3 = ldsu(Xlo, so + 328);
#pragma unroll
                for (int j = 0; j < 2; j++) {
                    mma16816(acc[i][j], ah0, ah1, ah2, ah3, bh[j][0], bh[j][1]);
                    mma16816(acc[i][j], al0, al1, al2, al3, bh[j][0], bh[j][1]);
                    mma16816(acc[i][j], ah0, ah1, ah2, ah3, bl[j][0], bl[j][1]);
                }
            }
        }
    }

#pragma unroll
    for (int i = 0; i < WM; i++) {
#pragma unroll
        for (int j = 0; j < 2; j++) {
            int f = f0 + (wn * 2 + j) * 8 + 2 * q;   // even
            float b0 = bias[f], b1 = bias[f + 1];
            int mr = m0 + (wm * WM + i) * 16 + g;
#pragma unroll
            for (int half = 0; half < 2; half++) {
                int m = mr + 8 * half;
                float2 v;
                v.x = acc[i][j][half * 2 + 0] + b0;
                v.y = acc[i][j][half * 2 + 1] + b1;
                if (MODE == 0) {
                    *reinterpret_cast<float2*>(out + (size_t)m * EE + f) = v;
                } else {
                    int b = m >> 4, s = m & 15, h = f >> 7, d = f & 127;
                    *reinterpret_cast<float2*>(
                        out + (((size_t)(b * HH + h)) * SS + s) * DD + d) = v;
                }
            }
        }
    }
}

__global__ void __launch_bounds__(256) qkv_gemm(const float* __restrict__ emb,
                                                const float* __restrict__ Wq,
                                                const float* __restrict__ Wk,
                                                const float* __restrict__ Wv,
                                                const float* __restrict__ bq,
                                                const float* __restrict__ bk,
                                                const float* __restrict__ bv,
                                                float* __restrict__ kout,
                                                float* __restrict__ vout) {
    const float* W;
    const float* bias;
    float* o;
    if (blockIdx.z == 0) { W = Wq; bias = bq; o = g_q; }
    else if (blockIdx.z == 1) { W = Wk; bias = bk; o = kout; }
    else { W = Wv; bias = bv; o = vout; }
    mma_gemm<2, 1>(emb, W, bias, o);
}

__global__ void __launch_bounds__(256) out_gemm(const float* __restrict__ Wo,
                                                const float* __restrict__ bo,
                                                float* __restrict__ out) {
    mma_gemm<1, 0>(g_ctx, Wo, bo, out);
}

// =============================================================================
// Flash attention — UNCHANGED from the 459-us passing version.
// =============================================================================
#define FL_QS   0
#define FL_K0   2112
#define FL_K1   6336
#define FL_V0   10560
#define FL_V1   14784
#define FL_SP   19008
#define FL_TOT  23232

__global__ void __launch_bounds__(256, 2) flash_kernel(const float* __restrict__ kc,
                                                       const float* __restrict__ vc,
                                                       const float* __restrict__ knew,
                                                       const float* __restrict__ vnew) {
    extern __shared__ float SM[];
    __shared__ float Ss[16 * 34];
    __shared__ float m_s[16], l_s[16], c_s[16];

    float* Qs = SM + FL_QS;
    float* SP = SM + FL_SP;
    float* FB = SM;

    int tid = threadIdx.x;
    int bh = blockIdx.x & 127;
    int split = blockIdx.x >> 7;

    int qgA = tid & 3;
    int kgA = (tid >> 2) & 7;
    int dgA = tid >> 5;
    int dg2 = tid & 15;
    int qg2 = (tid >> 4) & 3;
    int ksl = tid >> 6;
    int warp = tid >> 5;
    int lane = tid & 31;
    int jl = tid >> 3;
    int cl = tid & 7;

    auto issue_kv = [&](int tile, int buf) {
        bool tl = (tile == 128);
        const float* ksrc = !tl
            ? kc + ((size_t)bh * TCACHE + (size_t)tile * 32) * DD
            : knew + (size_t)bh * (SS * DD);
        const float* vsrc = !tl
            ? vc + ((size_t)bh * TCACHE + (size_t)tile * 32) * DD
            : vnew + (size_t)bh * (SS * DD);
        if (!tl || jl < 16) {
            float* Kd = SM + (buf ? FL_K1 : FL_K0) + jl * 132 + cl * 4;
            float* Vd = SM + (buf ? FL_V1 : FL_V0) + jl * 132 + cl * 4;
            const float* kg = ksrc + (size_t)jl * DD + cl * 4;
            const float* vg = vsrc + (size_t)jl * DD + cl * 4;
#pragma unroll
            for (int t = 0; t < 4; t++) {
                cp16(Kd + 32 * t, kg + 32 * t);
                cp16(Vd + 32 * t, vg + 32 * t);
            }
        }
    };

    {
        const float* qb = g_q + (size_t)bh * (SS * DD);
#pragma unroll
        for (int rep = 0; rep < 2; rep++) {
            int i = tid + 256 * rep;
            int q = (i * 4) >> 7, d = (i * 4) & 127;
            *reinterpret_cast<float4*>(&Qs[q * 132 + d]) =
                *reinterpret_cast<const float4*>(&qb[i * 4]);
        }
    }
    if (tid < 16) { m_s[tid] = -1e30f; l_s[tid] = 0.f; }

    const float scale = 0.08838834764831845f;
    const int t0 = split * 64;
    const int NT = split ? 65 : 64;

    ull o2[4][4] = {};

    issue_kv(t0, 0);
    cp_commit();

    for (int lt = 0; lt < NT; lt++) {
        int tile = t0 + lt;
        bool tail = (tile == 128);
        int cur = lt & 1;
        float* Ks = SM + (cur ? FL_K1 : FL_K0);
        float* Vw = SM + (cur ? FL_V1 : FL_V0);

        cp_wait0();
        __syncthreads();

        if (lt + 1 < NT) {
            issue_kv(tile + 1, cur ^ 1);
        }
        cp_commit();

        {
            ull acc[4][4] = {};
#pragma unroll
            for (int dp = 0; dp < 8; dp++) {
                ull qv[4];
#pragma unroll
                for (int qq = 0; qq < 4; qq++)
                    qv[qq] = *reinterpret_cast<const ull*>(
                        &Qs[(qgA * 4 + qq) * 132 + dgA * 16 + 2 * dp]);
#pragma unroll
                for (int kk = 0; kk < 4; kk++) {
                    ull kv = *reinterpret_cast<const ull*>(
                        &Ks[(kgA + 8 * kk) * 132 + dgA * 16 + 2 * dp]);
#pragma unroll
                    for (int qq = 0; qq < 4; qq++)
                        ffma2(acc[qq][kk], qv[qq], kv);
                }
            }
#pragma unroll
            for (int qq = 0; qq < 4; qq++)
#pragma unroll
                for (int kk = 0; kk < 4; kk++)
                    SP[dgA * 528 + (qgA * 4 + qq) * 33 + (kgA + 8 * kk)] =
                        lo32(acc[qq][kk]) + hi32(acc[qq][kk]);
        }
        __syncthreads();

#pragma unroll
        for (int rr = 0; rr < 2; rr++) {
            int row = warp + 8 * rr;
            float s = 0.f;
#pragma unroll
            for (int dg = 0; dg < 8; dg++) s += SP[dg * 528 + row * 33 + lane];
            s *= scale;
            if (tail && lane > row) s = -1e30f;
            float mx = s;
#pragma unroll
            for (int off = 16; off; off >>= 1)
                mx = fmaxf(mx, __shfl_xor_sync(0xffffffffu, mx, off));
            float mold = m_s[row];
            float mnew = fmaxf(mold, mx);
            float p = __expf(s - mnew);
            Ss[row * 34 + lane] = p;
            float sum = p;
#pragma unroll
            for (int off = 16; off; off >>= 1)
                sum += __shfl_xor_sync(0xffffffffu, sum, off);
            if (lane == 0) {
                float c = __expf(mold - mnew);
                m_s[row] = mnew;
                l_s[row] = l_s[row] * c + sum;
                c_s[row] = c;
            }
        }
        __syncthreads();

        {
            ull cf[4];
#pragma unroll
            for (int qq = 0; qq < 4; qq++) cf[qq] = dup2(c_s[qg2 * 4 + qq]);
#pragma unroll
            for (int qq = 0; qq < 4; qq++)
#pragma unroll
                for (int r = 0; r < 4; r++) fmul2(o2[qq][r], cf[qq]);

#pragma unroll
            for (int jj = 0; jj < 8; jj++) {
                int j = ksl * 8 + jj;
                ull pf[4];
#pragma unroll
                for (int qq = 0; qq < 4; qq++)
                    pf[qq] = dup2(Ss[(qg2 * 4 + qq) * 34 + j]);
#pragma unroll
                for (int r = 0; r < 4; r++) {
                    ull vv = *reinterpret_cast<const ull*>(
                        &Vw[j * 132 + 2 * dg2 + 32 * r]);
#pragma unroll
                    for (int qq = 0; qq < 4; qq++) ffma2(o2[qq][r], pf[qq], vv);
                }
            }
        }
    }

    __syncthreads();
    if (tid < 16) {
        g_ml[((size_t)(split * 128 + bh) * 16 + tid) * 2 + 0] = m_s[tid];
        g_ml[((size_t)(split * 128 + bh) * 16 + tid) * 2 + 1] = l_s[tid];
    }
#pragma unroll
    for (int qq = 0; qq < 4; qq++)
#pragma unroll
        for (int r = 0; r < 4; r++) {
            FB[tid * 33 + qq * 8 + r * 2]     = lo32(o2[qq][r]);
            FB[tid * 33 + qq * 8 + r * 2 + 1] = hi32(o2[qq][r]);
        }
    __syncthreads();
    if (tid < 64) {
        float* dst = g_part + ((size_t)(split * 128 + bh)) * (SS * DD);
#pragma unroll
        for (int i = 0; i < 32; i++) {
            float v = FB[tid * 33 + i] + FB[(tid + 64) * 33 + i] +
                      FB[(tid + 128) * 33 + i] + FB[(tid + 192) * 33 + i];
            int qq = i >> 3, r = (i >> 1) & 3, lh = i & 1;
            int q = qg2 * 4 + qq;
            int d = 2 * dg2 + 32 * r + lh;
            dst[q * DD + d] = v;
        }
    }
}

// =============================================================================
// Combine splits (unchanged)
// =============================================================================
__global__ void __launch_bounds__(256) combine_kernel() {
    __shared__ float w0s[16], w1s[16];
    int bh = blockIdx.x;
    int tid = threadIdx.x;
    if (tid < 16) {
        float m0 = g_ml[((size_t)bh * 16 + tid) * 2 + 0];
        float l0 = g_ml[((size_t)bh * 16 + tid) * 2 + 1];
        float m1 = g_ml[((size_t)(128 + bh) * 16 + tid) * 2 + 0];
        float l1 = g_ml[((size_t)(128 + bh) * 16 + tid) * 2 + 1];
        float M = fmaxf(m0, m1);
        float e0 = __expf(m0 - M), e1 = __expf(m1 - M);
        float inv = 1.f / (l0 * e0 + l1 * e1);
        w0s[tid] = e0 * inv;
        w1s[tid] = e1 * inv;
    }
    __syncthreads();
    int b = bh >> 4, h = bh & 15;
    const float* p0 = g_part + (size_t)bh * (SS * DD);
    const float* p1 = g_part + (size_t)(128 + bh) * (SS * DD);
    for (int idx = tid; idx < SS * DD; idx += 256) {
        int q = idx >> 7;
        g_ctx[((size_t)(b * SS + q)) * EE + h * DD + (idx & 127)] =
            p0[idx] * w0s[q] + p1[idx] * w1s[q];
    }
}

// ---------------- launch -----------------------------------------------------
extern "C" void kernel_launch(void* const* d_in, const int* in_sizes, int n_in,
                              void* d_out, int out_size) {
    const float* emb = (const float*)d_in[0];
    const float* kc  = (const float*)d_in[1];
    const float* vc  = (const float*)d_in[2];
    const float* Wq  = (const float*)d_in[3];
    const float* bq  = (const float*)d_in[4];
    const float* Wk  = (const float*)d_in[5];
    const float* bk  = (const float*)d_in[6];
    const float* Wv  = (const float*)d_in[7];
    const float* bv  = (const float*)d_in[8];
    const float* Wo  = (const float*)d_in[9];
    const float* bo  = (const float*)d_in[10];

    float* out  = (float*)d_out;          // (8,16,2048)
    float* kout = out + MM * EE;          // k_new (8,16,16,128)
    float* vout = out + 2 * MM * EE;      // v_new (8,16,16,128)

    (void)cudaFuncSetAttribute(flash_kernel,
                               cudaFuncAttributeMaxDynamicSharedMemorySize,
                               FL_TOT * (int)sizeof(float));

    qkv_gemm<<<dim3(32, 2, 3), 256>>>(emb, Wq, Wk, Wv, bq, bk, bv, kout, vout);
    flash_kernel<<<256, 256, FL_TOT * sizeof(float)>>>(kc, vc, kout, vout);
    combine_kernel<<<128, 256>>>();
    out_gemm<<<dim3(32, 4), 256>>>(Wo, bo, out);
}

// round 17
// speedup vs baseline: 1.5682x; 1.1508x over previous
#include <cuda_runtime.h>
#include <math.h>

#define BB 8
#define SS 16
#define HH 16
#define DD 128
#define EE 2048
#define MM 128          // B*S rows
#define TCACHE 4096

typedef unsigned long long ull;

// ---------------- scratch (device globals) ----------------------------------
__device__ float g_q[MM * EE];                // (b,h,s,d)
__device__ float g_ctx[MM * EE];              // (b,s,e)
__device__ float g_part[2 * 128 * 16 * 128];  // [split][bh][q][d] unnormalized
__device__ float g_ml[2 * 128 * 16 * 2];      // [split][bh][q][{m,l}]

// ---------------- bf16 split + mma helpers -----------------------------------
__device__ __forceinline__ void cvt_split(float x0, float x1,
                                          unsigned& hi, unsigned& lo) {
    asm("cvt.rn.bf16x2.f32 %0, %1, %2;" : "=r"(hi) : "f"(x1), "f"(x0));
    float h0 = __uint_as_float(hi << 16);
    float h1 = __uint_as_float(hi & 0xffff0000u);
    float l0 = x0 - h0;
    float l1 = x1 - h1;
    asm("cvt.rn.bf16x2.f32 %0, %1, %2;" : "=r"(lo) : "f"(l1), "f"(l0));
}

__device__ __forceinline__ void split1(float x, unsigned short& h,
                                       unsigned short& l) {
    asm("cvt.rn.bf16.f32 %0, %1;" : "=h"(h) : "f"(x));
    float hf = __uint_as_float(((unsigned)h) << 16);
    float r = x - hf;
    asm("cvt.rn.bf16.f32 %0, %1;" : "=h"(l) : "f"(r));
}

__device__ __forceinline__ void mma16816(float* c,
                                         unsigned a0, unsigned a1,
                                         unsigned a2, unsigned a3,
                                         unsigned b0, unsigned b1) {
    asm("mma.sync.aligned.m16n8k16.row.col.f32.bf16.bf16.f32 "
        "{%0,%1,%2,%3}, {%4,%5,%6,%7}, {%8,%9}, {%0,%1,%2,%3};"
        : "+f"(c[0]), "+f"(c[1]), "+f"(c[2]), "+f"(c[3])
        : "r"(a0), "r"(a1), "r"(a2), "r"(a3), "r"(b0), "r"(b1));
}

__device__ __forceinline__ unsigned ldsu(const unsigned short* p, int soff) {
    return *reinterpret_cast<const unsigned*>(p + soff);
}
__device__ __forceinline__ void stsu(unsigned short* p, int soff, unsigned v) {
    *reinterpret_cast<unsigned*>(p + soff) = v;
}

// =============================================================================
// Split-bf16 tensor-core GEMM (unchanged from the 373-us passing version).
// =============================================================================
template <int WM, int MODE>
__device__ __forceinline__ void mma_gemm(const float* __restrict__ X,
                                         const float* __restrict__ W,
                                         const float* __restrict__ bias,
                                         float* __restrict__ out) {
    constexpr int MROWS = WM * 32;
    __shared__ __align__(16) unsigned short Xhi[MROWS * 40];
    __shared__ __align__(16) unsigned short Xlo[MROWS * 40];
    __shared__ __align__(16) unsigned short Whi[64 * 40];
    __shared__ __align__(16) unsigned short Wlo[64 * 40];

    const int tid = threadIdx.x;
    const int m0 = blockIdx.y * MROWS;
    const int f0 = blockIdx.x * 64;
    const int w = tid >> 5, lane = tid & 31, g = lane >> 2, q = lane & 3;
    const int wm = w >> 2, wn = w & 3;

    const int lrw = tid >> 2, lsw = tid & 3;
    const int lrx = (WM == 2) ? lrw : (tid >> 3);
    const int lcx = (WM == 2) ? lsw * 8 : (tid & 7) * 4;

    const float* Wp = W + (size_t)(f0 + lrw) * EE + lsw * 8;
    const float* Xp = X + (size_t)(m0 + lrx) * EE + lcx;

    float4 wreg[2], xreg[2];
    wreg[0] = *reinterpret_cast<const float4*>(Wp);
    wreg[1] = *reinterpret_cast<const float4*>(Wp + 4);
    xreg[0] = *reinterpret_cast<const float4*>(Xp);
    if constexpr (WM == 2) xreg[1] = *reinterpret_cast<const float4*>(Xp + 4);

    float acc[WM][2][4];
#pragma unroll
    for (int i = 0; i < WM; i++)
#pragma unroll
        for (int j = 0; j < 2; j++)
#pragma unroll
            for (int r = 0; r < 4; r++) acc[i][j][r] = 0.f;

    for (int kt = 0; kt < EE; kt += 32) {
        __syncthreads();
        {
            unsigned hi, lo;
            int so = lrw * 40 + lsw * 8;
            cvt_split(wreg[0].x, wreg[0].y, hi, lo); stsu(Whi, so,     hi); stsu(Wlo, so,     lo);
            cvt_split(wreg[0].z, wreg[0].w, hi, lo); stsu(Whi, so + 2, hi); stsu(Wlo, so + 2, lo);
            cvt_split(wreg[1].x, wreg[1].y, hi, lo); stsu(Whi, so + 4, hi); stsu(Wlo, so + 4, lo);
            cvt_split(wreg[1].z, wreg[1].w, hi, lo); stsu(Whi, so + 6, hi); stsu(Wlo, so + 6, lo);
            int sx = lrx * 40 + lcx;
            cvt_split(xreg[0].x, xreg[0].y, hi, lo); stsu(Xhi, sx,     hi); stsu(Xlo, sx,     lo);
            cvt_split(xreg[0].z, xreg[0].w, hi, lo); stsu(Xhi, sx + 2, hi); stsu(Xlo, sx + 2, lo);
            if constexpr (WM == 2) {
                cvt_split(xreg[1].x, xreg[1].y, hi, lo); stsu(Xhi, sx + 4, hi); stsu(Xlo, sx + 4, lo);
                cvt_split(xreg[1].z, xreg[1].w, hi, lo); stsu(Xhi, sx + 6, hi); stsu(Xlo, sx + 6, lo);
            }
        }
        __syncthreads();
        if (kt + 32 < EE) {
            wreg[0] = *reinterpret_cast<const float4*>(Wp + kt + 32);
            wreg[1] = *reinterpret_cast<const float4*>(Wp + kt + 36);
            xreg[0] = *reinterpret_cast<const float4*>(Xp + kt + 32);
            if constexpr (WM == 2)
                xreg[1] = *reinterpret_cast<const float4*>(Xp + kt + 36);
        }
#pragma unroll
        for (int ks = 0; ks < 2; ks++) {
            unsigned bh[2][2], bl[2][2];
#pragma unroll
            for (int j = 0; j < 2; j++) {
                int so = ((wn * 2 + j) * 8 + g) * 40 + 2 * q + 16 * ks;
                bh[j][0] = ldsu(Whi, so); bh[j][1] = ldsu(Whi, so + 8);
                bl[j][0] = ldsu(Wlo, so); bl[j][1] = ldsu(Wlo, so + 8);
            }
#pragma unroll
            for (int i = 0; i < WM; i++) {
                int so = ((wm * WM + i) * 16 + g) * 40 + 2 * q + 16 * ks;
                unsigned ah0 = ldsu(Xhi, so),     ah1 = ldsu(Xhi, so + 320);
                unsigned ah2 = ldsu(Xhi, so + 8), ah3 = ldsu(Xhi, so + 328);
                unsigned al0 = ldsu(Xlo, so),     al1 = ldsu(Xlo, so + 320);
                unsigned al2 = ldsu(Xlo, so + 8), al3 = ldsu(Xlo, so + 328);
#pragma unroll
                for (int j = 0; j < 2; j++) {
                    mma16816(acc[i][j], ah0, ah1, ah2, ah3, bh[j][0], bh[j][1]);
                    mma16816(acc[i][j], al0, al1, al2, al3, bh[j][0], bh[j][1]);
                    mma16816(acc[i][j], ah0, ah1, ah2, ah3, bl[j][0], bl[j][1]);
                }
            }
        }
    }

#pragma unroll
    for (int i = 0; i < WM; i++) {
#pragma unroll
        for (int j = 0; j < 2; j++) {
            int f = f0 + (wn * 2 + j) * 8 + 2 * q;
            float b0 = bias[f], b1 = bias[f + 1];
            int mr = m0 + (wm * WM + i) * 16 + g;
#pragma unroll
            for (int half = 0; half < 2; half++) {
                int m = mr + 8 * half;
                float2 v;
                v.x = acc[i][j][half * 2 + 0] + b0;
                v.y = acc[i][j][half * 2 + 1] + b1;
                if (MODE == 0) {
                    *reinterpret_cast<float2*>(out + (size_t)m * EE + f) = v;
                } else {
                    int b = m >> 4, s = m & 15, h = f >> 7, d = f & 127;
                    *reinterpret_cast<float2*>(
                        out + (((size_t)(b * HH + h)) * SS + s) * DD + d) = v;
                }
            }
        }
    }
}

__global__ void __launch_bounds__(256) qkv_gemm(const float* __restrict__ emb,
                                                const float* __restrict__ Wq,
                                                const float* __restrict__ Wk,
                                                const float* __restrict__ Wv,
                                                const float* __restrict__ bq,
                                                const float* __restrict__ bk,
                                                const float* __restrict__ bv,
                                                float* __restrict__ kout,
                                                float* __restrict__ vout) {
    const float* W;
    const float* bias;
    float* o;
    if (blockIdx.z == 0) { W = Wq; bias = bq; o = g_q; }
    else if (blockIdx.z == 1) { W = Wk; bias = bk; o = kout; }
    else { W = Wv; bias = bv; o = vout; }
    mma_gemm<2, 1>(emb, W, bias, o);
}

__global__ void __launch_bounds__(256) out_gemm(const float* __restrict__ Wo,
                                                const float* __restrict__ bo,
                                                float* __restrict__ out) {
    mma_gemm<1, 0>(g_ctx, Wo, bo, out);
}

// =============================================================================
// Flash attention on tensor cores. Split-KV x2, 256 thr (8 warps), 32-key
// tiles, 2 CTAs/SM. Scores: 8 warps = 4 ntiles x 2 d-halves, 12 mma each,
// fp32 C partials summed in softmax. PV: 8 warps x 2 d-tiles, 12 mma each,
// O stays in C fragments (8 regs) across all tiles. P split bf16 hi/lo; K
// converted reg->smem; V transposed via fp32 staging to [d][key].
// Smem offsets (floats):
//   QH 0 (1088) QL 1088 | KH 2176 (2176) KL 4352 | VH 6528 (2560) VL 9088
//   VS 11648 (4224) | SC 15872 (8*132) | PH 16928 (320) PL 17248 (320)
//   total 17568 fl = 70272 B (x2 CTAs = 140 KB)
// =============================================================================
#define FQH 0
#define FQL 1088
#define FKH 2176
#define FKL 4352
#define FVH 6528
#define FVL 9088
#define FVS 11648
#define FSC 15872
#define FPH 16928
#define FPL 17248
#define FL_TOT 17568

__global__ void __launch_bounds__(256, 2) flash_kernel(const float* __restrict__ kc,
                                                       const float* __restrict__ vc,
                                                       const float* __restrict__ knew,
                                                       const float* __restrict__ vnew) {
    extern __shared__ float SM[];
    __shared__ float m_s[16], l_s[16], c_s[16];

    unsigned short* QhiS = reinterpret_cast<unsigned short*>(SM + FQH);
    unsigned short* QloS = reinterpret_cast<unsigned short*>(SM + FQL);
    unsigned short* KhiS = reinterpret_cast<unsigned short*>(SM + FKH);
    unsigned short* KloS = reinterpret_cast<unsigned short*>(SM + FKL);
    unsigned short* VhiS = reinterpret_cast<unsigned short*>(SM + FVH);
    unsigned short* VloS = reinterpret_cast<unsigned short*>(SM + FVL);
    unsigned short* PhiS = reinterpret_cast<unsigned short*>(SM + FPH);
    unsigned short* PloS = reinterpret_cast<unsigned short*>(SM + FPL);

    const int tid = threadIdx.x;
    const int bh = blockIdx.x & 127;
    const int split = blockIdx.x >> 7;
    const int w = tid >> 5, lane = tid & 31, g = lane >> 2, q = lane & 3;

    // loader ids
    const int jl = tid >> 3;           // key row 0..31
    const int cl = tid & 7;            // float4 chunks at cols cl*4 + 32t
    // V transpose ids
    const int td = tid & 127;          // d
    const int tj0 = tid >> 7;          // 0/1

    // ---- Q -> bf16 hi/lo (once) --------------------------------------------
    {
        const float* qb = g_q + (size_t)bh * (SS * DD);
#pragma unroll
        for (int i = 0; i < 4; i++) {
            int p = tid + 256 * i;            // pair index 0..1023
            int row = p >> 6, col = (p * 2) & 127;
            unsigned hi, lo;
            cvt_split(qb[p * 2], qb[p * 2 + 1], hi, lo);
            stsu(QhiS, row * 136 + col, hi);
            stsu(QloS, row * 136 + col, lo);
        }
    }
    if (tid < 16) { m_s[tid] = -1e30f; l_s[tid] = 0.f; }

    const float scale = 0.08838834764831845f;  // 1/sqrt(128)
    const int t0 = split * 64;
    const int NT = split ? 65 : 64;            // split 1 owns the tail tile

    float o[2][4] = {};                        // O fragments: 2 d-tiles/warp

    // prologue: LDG tile t0 into registers
    float4 kpre[4], vpre[4];
    {
        const float* ks0 = kc + ((size_t)bh * TCACHE + (size_t)t0 * 32) * DD;
        const float* vs0 = vc + ((size_t)bh * TCACHE + (size_t)t0 * 32) * DD;
#pragma unroll
        for (int t = 0; t < 4; t++) {
            kpre[t] = *reinterpret_cast<const float4*>(ks0 + (size_t)jl * DD + cl * 4 + 32 * t);
            vpre[t] = *reinterpret_cast<const float4*>(vs0 + (size_t)jl * DD + cl * 4 + 32 * t);
        }
    }

    for (int lt = 0; lt < NT; lt++) {
        int tile = t0 + lt;
        bool tail = (tile == 128);
        bool on = !tail || (jl < 16);

        __syncthreads();  // (A) prior tile's mma reads complete

        // K regs -> bf16 smem; V regs -> fp32 staging
        if (on) {
#pragma unroll
            for (int t = 0; t < 4; t++) {
                unsigned hi, lo;
                int so = jl * 136 + cl * 4 + 32 * t;
                cvt_split(kpre[t].x, kpre[t].y, hi, lo);
                stsu(KhiS, so, hi); stsu(KloS, so, lo);
                cvt_split(kpre[t].z, kpre[t].w, hi, lo);
                stsu(KhiS, so + 2, hi); stsu(KloS, so + 2, lo);
                *reinterpret_cast<float4*>(&SM[FVS + jl * 132 + cl * 4 + 32 * t]) = vpre[t];
            }
        }
        __syncthreads();  // (B) Khi/Klo + Vstg visible; kpre/vpre free

        // issue LDG for next tile (lands during scores+softmax+PV)
        if (lt + 1 < NT) {
            int tn = tile + 1;
            bool ntail = (tn == 128);
            const float* ksrc = !ntail
                ? kc + ((size_t)bh * TCACHE + (size_t)tn * 32) * DD
                : knew + (size_t)bh * (SS * DD);
            const float* vsrc = !ntail
                ? vc + ((size_t)bh * TCACHE + (size_t)tn * 32) * DD
                : vnew + (size_t)bh * (SS * DD);
            if (!ntail || jl < 16) {
#pragma unroll
                for (int t = 0; t < 4; t++) {
                    kpre[t] = *reinterpret_cast<const float4*>(
                        ksrc + (size_t)jl * DD + cl * 4 + 32 * t);
                    vpre[t] = *reinterpret_cast<const float4*>(
                        vsrc + (size_t)jl * DD + cl * 4 + 32 * t);
                }
            }
        }

        // V transpose: fp32 staging [key][d] -> bf16 [d][key]
        {
#pragma unroll
            for (int i = 0; i < 8; i++) {
                int jp = tj0 + 2 * i;          // key pair 0..15
                float v0 = SM[FVS + (2 * jp) * 132 + td];
                float v1 = SM[FVS + (2 * jp + 1) * 132 + td];
                unsigned hi, lo;
                cvt_split(v0, v1, hi, lo);
                stsu(VhiS, td * 40 + 2 * jp, hi);
                stsu(VloS, td * 40 + 2 * jp, lo);
            }
        }
        __syncthreads();  // (C) Vt visible

        // scores: warp w -> ntile nt=w&3, d-half dh=w>>2; 12 mma
        {
            int nt = w & 3, dh = w >> 2;
            float sc[4] = {};
#pragma unroll
            for (int c = 0; c < 4; c++) {
                int dof = dh * 64 + c * 16;
                int ao = g * 136 + dof + 2 * q;
                unsigned ah0 = ldsu(QhiS, ao),        ah1 = ldsu(QhiS, ao + 1088);
                unsigned ah2 = ldsu(QhiS, ao + 8),    ah3 = ldsu(QhiS, ao + 1096);
                unsigned al0 = ldsu(QloS, ao),        al1 = ldsu(QloS, ao + 1088);
                unsigned al2 = ldsu(QloS, ao + 8),    al3 = ldsu(QloS, ao + 1096);
                int bo = (nt * 8 + g) * 136 + dof + 2 * q;
                unsigned bh0 = ldsu(KhiS, bo), bh1 = ldsu(KhiS, bo + 8);
                unsigned bl0 = ldsu(KloS, bo), bl1 = ldsu(KloS, bo + 8);
                mma16816(sc, ah0, ah1, ah2, ah3, bh0, bh1);
                mma16816(sc, al0, al1, al2, al3, bh0, bh1);
                mma16816(sc, ah0, ah1, ah2, ah3, bl0, bl1);
            }
            SM[FSC + w * 132 + g * 8 + 2 * q]           = sc[0];
            SM[FSC + w * 132 + g * 8 + 2 * q + 1]       = sc[1];
            SM[FSC + w * 132 + (g + 8) * 8 + 2 * q]     = sc[2];
            SM[FSC + w * 132 + (g + 8) * 8 + 2 * q + 1] = sc[3];
        }
        __syncthreads();  // (D) score partials visible

        // softmax: warp w owns rows w, w+8; lane = key 0..31
        {
            int nt = lane >> 3, kc8 = lane & 7;
#pragma unroll
            for (int rr = 0; rr < 2; rr++) {
                int row = w + 8 * rr;
                float s = SM[FSC + nt * 132 + row * 8 + kc8] +
                          SM[FSC + (4 + nt) * 132 + row * 8 + kc8];
                s *= scale;
                if (tail && lane > row) s = -1e30f;
                float mx = s;
#pragma unroll
                for (int off = 16; off; off >>= 1)
                    mx = fmaxf(mx, __shfl_xor_sync(0xffffffffu, mx, off));
                float mold = m_s[row];
                float mnew = fmaxf(mold, mx);
                float p = __expf(s - mnew);
                unsigned short ph, pl;
                split1(p, ph, pl);
                PhiS[row * 40 + lane] = ph;
                PloS[row * 40 + lane] = pl;
                float sum = p;
#pragma unroll
                for (int off = 16; off; off >>= 1)
                    sum += __shfl_xor_sync(0xffffffffu, sum, off);
                if (lane == 0) {
                    float c = __expf(mold - mnew);
                    m_s[row] = mnew;
                    l_s[row] = l_s[row] * c + sum;
                    c_s[row] = c;
                }
            }
        }
        __syncthreads();  // (E) P + c ready

        // PV: warp w -> d-tiles 2w, 2w+1; 12 mma
        {
            float c0 = c_s[g], c1 = c_s[g + 8];
#pragma unroll
            for (int t = 0; t < 2; t++) {
                o[t][0] *= c0; o[t][1] *= c0;
                o[t][2] *= c1; o[t][3] *= c1;
            }
#pragma unroll
            for (int ks = 0; ks < 2; ks++) {
                int ao = g * 40 + 16 * ks + 2 * q;
                unsigned ph0 = ldsu(PhiS, ao),     ph1 = ldsu(PhiS, ao + 320);
                unsigned ph2 = ldsu(PhiS, ao + 8), ph3 = ldsu(PhiS, ao + 328);
                unsigned pl0 = ldsu(PloS, ao),     pl1 = ldsu(PloS, ao + 320);
                unsigned pl2 = ldsu(PloS, ao + 8), pl3 = ldsu(PloS, ao + 328);
#pragma unroll
                for (int t = 0; t < 2; t++) {
                    int dt = 2 * w + t;
                    int bo = (dt * 8 + g) * 40 + 16 * ks + 2 * q;
                    unsigned vh0 = ldsu(VhiS, bo), vh1 = ldsu(VhiS, bo + 8);
                    unsigned vl0 = ldsu(VloS, bo), vl1 = ldsu(VloS, bo + 8);
                    mma16816(o[t], ph0, ph1, ph2, ph3, vh0, vh1);
                    mma16816(o[t], pl0, pl1, pl2, pl3, vh0, vh1);
                    mma16816(o[t], ph0, ph1, ph2, ph3, vl0, vl1);
                }
            }
        }
    }

    // epilogue: (m,l) + unnormalized O straight from fragments
    __syncthreads();
    if (tid < 16) {
        g_ml[((size_t)(split * 128 + bh) * 16 + tid) * 2 + 0] = m_s[tid];
        g_ml[((size_t)(split * 128 + bh) * 16 + tid) * 2 + 1] = l_s[tid];
    }
    {
        float* dst = g_part + (size_t)(split * 128 + bh) * (SS * DD);
#pragma unroll
        for (int t = 0; t < 2; t++) {
            int col = (2 * w + t) * 8 + 2 * q;
            float2 v0 = { o[t][0], o[t][1] };
            float2 v1 = { o[t][2], o[t][3] };
            *reinterpret_cast<float2*>(&dst[g * DD + col]) = v0;
            *reinterpret_cast<float2*>(&dst[(g + 8) * DD + col]) = v1;
        }
    }
}

// =============================================================================
// Combine splits (unchanged)
// =============================================================================
__global__ void __launch_bounds__(256) combine_kernel() {
    __shared__ float w0s[16], w1s[16];
    int bh = blockIdx.x;
    int tid = threadIdx.x;
    if (tid < 16) {
        float m0 = g_ml[((size_t)bh * 16 + tid) * 2 + 0];
        float l0 = g_ml[((size_t)bh * 16 + tid) * 2 + 1];
        float m1 = g_ml[((size_t)(128 + bh) * 16 + tid) * 2 + 0];
        float l1 = g_ml[((size_t)(128 + bh) * 16 + tid) * 2 + 1];
        float M = fmaxf(m0, m1);
        float e0 = __expf(m0 - M), e1 = __expf(m1 - M);
        float inv = 1.f / (l0 * e0 + l1 * e1);
        w0s[tid] = e0 * inv;
        w1s[tid] = e1 * inv;
    }
    __syncthreads();
    int b = bh >> 4, h = bh & 15;
    const float* p0 = g_part + (size_t)bh * (SS * DD);
    const float* p1 = g_part + (size_t)(128 + bh) * (SS * DD);
    for (int idx = tid; idx < SS * DD; idx += 256) {
        int q = idx >> 7;
        g_ctx[((size_t)(b * SS + q)) * EE + h * DD + (idx & 127)] =
            p0[idx] * w0s[q] + p1[idx] * w1s[q];
    }
}

// ---------------- launch -----------------------------------------------------
extern "C" void kernel_launch(void* const* d_in, const int* in_sizes, int n_in,
                              void* d_out, int out_size) {
    const float* emb = (const float*)d_in[0];
    const float* kc  = (const float*)d_in[1];
    const float* vc  = (const float*)d_in[2];
    const float* Wq  = (const float*)d_in[3];
    const float* bq  = (const float*)d_in[4];
    const float* Wk  = (const float*)d_in[5];
    const float* bk  = (const float*)d_in[6];
    const float* Wv  = (const float*)d_in[7];
    const float* bv  = (const float*)d_in[8];
    const float* Wo  = (const float*)d_in[9];
    const float* bo  = (const float*)d_in[10];

    float* out  = (float*)d_out;          // (8,16,2048)
    float* kout = out + MM * EE;          // k_new (8,16,16,128)
    float* vout = out + 2 * MM * EE;      // v_new (8,16,16,128)

    (void)cudaFuncSetAttribute(flash_kernel,
                               cudaFuncAttributeMaxDynamicSharedMemorySize,
                               FL_TOT * (int)sizeof(float));

    qkv_gemm<<<dim3(32, 2, 3), 256>>>(emb, Wq, Wk, Wv, bq, bk, bv, kout, vout);
    flash_kernel<<<256, 256, FL_TOT * sizeof(float)>>>(kc, vc, kout, vout);
    combine_kernel<<<128, 256>>>();
    out_gemm<<<dim3(32, 4), 256>>>(Wo, bo, out);
}